// round 11
// baseline (speedup 1.0000x reference)
#include <cuda_runtime.h>
#include <math.h>

// ---------------- problem constants ----------------
#define NTOT   102400          // B*T*NODES
#define ETOT   1638400         // edges
#define BATCH  8
#define TSTEPS 32
#define NODES  400
#define NSEQ   (BATCH*NODES)   // 3200
#define D_IN   64
#define L1F    96
#define L2F    64
#define GATES  256             // 4*64
#define FC1F   128
#define FC2F   3

typedef unsigned long long u64;

// ---------------- packed f32x2 helpers (sm_103a FFMA2 path) ----------------
__device__ __forceinline__ u64 dup2(float v) {
    u64 r; asm("mov.b64 %0, {%1, %1};" : "=l"(r) : "f"(v)); return r;
}
__device__ __forceinline__ u64 pk2(float x, float y) {
    u64 r; asm("mov.b64 %0, {%1, %2};" : "=l"(r) : "f"(x), "f"(y)); return r;
}
__device__ __forceinline__ void up2(u64 v, float& x, float& y) {
    asm("mov.b64 {%0, %1}, %2;" : "=f"(x), "=f"(y) : "l"(v));
}
__device__ __forceinline__ void fma2(u64& d, u64 a, u64 b) {
    asm("fma.rn.f32x2 %0, %1, %2, %0;" : "+l"(d) : "l"(a), "l"(b));
}

// ---------------- device scratch (static: allowed) ----------------
__device__ float g_colsum[64];
__device__ float g_colsumsq[64];
__device__ __align__(16) float g_mean[64];
__device__ __align__(16) float g_rstd[64];
__device__ int   g_counts[NTOT];
__device__ int   g_rowptr[NTOT + 1];
__device__ int   g_cursor[NTOT];
__device__ int   g_bsums[128];
__device__ float g_deg[NTOT];
__device__ float g_dis[NTOT];
__device__ __align__(16) int2  g_csr[ETOT];          // {src, float_bits(w*dis[src])}
__device__ __align__(16) float g_aggx [(size_t)NTOT * D_IN];
__device__ __align__(16) float g_h1   [(size_t)NTOT * L1F];
__device__ __align__(16) float g_h2pre[(size_t)NTOT * L2F];
__device__ __align__(16) float g_h2   [(size_t)NTOT * L2F];
__device__ __align__(16) float g_xg   [(size_t)NTOT * GATES];

// ---------------- init ----------------
__global__ void init_kernel() {
    int gid = blockIdx.x * blockDim.x + threadIdx.x;
    if (gid < NTOT) { g_counts[gid] = 0; g_deg[gid] = 1.0f; }
    if (gid < 64)   { g_colsum[gid] = 0.f; g_colsumsq[gid] = 0.f; }
}

// ---------------- column stats (mean/std, ddof=1) ----------------
__global__ void col_stats_kernel(const float* __restrict__ x) {
    __shared__ float ssum[256], ssq[256];
    int c  = threadIdx.x & 63;
    int rr = threadIdx.x >> 6;
    float s = 0.f, q = 0.f;
    for (int row = blockIdx.x * 4 + rr; row < NTOT; row += gridDim.x * 4) {
        float v = x[(size_t)row * 64 + c];
        s += v; q += v * v;
    }
    ssum[threadIdx.x] = s; ssq[threadIdx.x] = q;
    __syncthreads();
    if (threadIdx.x < 64) {
        float S = ssum[threadIdx.x] + ssum[threadIdx.x + 64] + ssum[threadIdx.x + 128] + ssum[threadIdx.x + 192];
        float Q = ssq [threadIdx.x] + ssq [threadIdx.x + 64] + ssq [threadIdx.x + 128] + ssq [threadIdx.x + 192];
        atomicAdd(&g_colsum[threadIdx.x], S);
        atomicAdd(&g_colsumsq[threadIdx.x], Q);
    }
}

__global__ void stats_finalize_kernel() {
    int c = threadIdx.x;
    if (c < 64) {
        float n = (float)NTOT;
        float mean = g_colsum[c] / n;
        float var  = (g_colsumsq[c] - n * mean * mean) / (n - 1.0f);
        g_mean[c] = mean;
        g_rstd[c] = rsqrtf(var);
    }
}

// ---------------- edge pass 1: histogram + weighted degree ----------------
__global__ void edge_pass1_kernel(const int* __restrict__ ei, const float* __restrict__ ea) {
    int e = blockIdx.x * blockDim.x + threadIdx.x;
    if (e >= ETOT) return;
    int dst = ei[ETOT + e];
    float w = fabsf(((const float2*)ea)[e].x);
    atomicAdd(&g_counts[dst], 1);
    atomicAdd(&g_deg[dst], w);
}

// ---------------- scan (exclusive) over counts ----------------
__global__ void scan1_kernel() {
    __shared__ int tmp[1024];
    int gid = blockIdx.x * 1024 + threadIdx.x;
    int v = g_counts[gid];
    tmp[threadIdx.x] = v;
    __syncthreads();
    int val = v;
    for (int off = 1; off < 1024; off <<= 1) {
        int add = (threadIdx.x >= off) ? tmp[threadIdx.x - off] : 0;
        __syncthreads();
        val += add;
        tmp[threadIdx.x] = val;
        __syncthreads();
    }
    g_rowptr[gid] = val - v;           // exclusive, local to block
    if (threadIdx.x == 1023) g_bsums[blockIdx.x] = val;
}

__global__ void scan2_kernel() {
    __shared__ int tmp[128];
    int t = threadIdx.x;
    int v = (t < NTOT / 1024) ? g_bsums[t] : 0;
    tmp[t] = v;
    __syncthreads();
    int val = v;
    for (int off = 1; off < 128; off <<= 1) {
        int add = (t >= off) ? tmp[t - off] : 0;
        __syncthreads();
        val += add;
        tmp[t] = val;
        __syncthreads();
    }
    if (t < NTOT / 1024) g_bsums[t] = val - v;   // exclusive
}

__global__ void scan3_kernel() {
    int gid = blockIdx.x * blockDim.x + threadIdx.x;
    if (gid >= NTOT) return;
    int rp = g_rowptr[gid] + g_bsums[gid >> 10];
    g_rowptr[gid] = rp;
    g_cursor[gid] = rp;
    g_dis[gid] = rsqrtf(g_deg[gid]);   // deg >= 1 always (self loop weight 1)
    if (gid == 0) g_rowptr[NTOT] = ETOT;
}

// ---------------- edge pass 2: scatter into CSR (packed int2, w pre-scaled by dis[src]) ----------------
__global__ void edge_scatter_kernel(const int* __restrict__ ei, const float* __restrict__ ea) {
    int e = blockIdx.x * blockDim.x + threadIdx.x;
    if (e >= ETOT) return;
    int dst = ei[ETOT + e];
    int src = ei[e];
    float w = fabsf(((const float2*)ea)[e].x) * g_dis[src];
    int pos = atomicAdd(&g_cursor[dst], 1);
    g_csr[pos] = make_int2(src, __float_as_int(w));
}

// ---------------- panel-resident SGEMM with packed f32x2 FMA ----------------
template<int K, int BN, int NTILES, bool TRANSB, bool RELU>
__global__ void gemmP_kernel(const float* __restrict__ A, const float* __restrict__ Bm,
                             const float* __restrict__ bias, const float* __restrict__ bias2,
                             float* __restrict__ C) {
    constexpr int Nout = BN * NTILES;
    constexpr int TX = BN / 4;
    constexpr int THREADS = TX * 16;
    constexpr int SA = 132;            // float4-aligned rows
    constexpr int SB = BN + 4;
    extern __shared__ float smem[];
    float* sA = smem;                  // [K][SA]  (k-major)
    float* sB = smem + K * SA;         // [K][SB]

    int tid = threadIdx.x;
    int m0 = blockIdx.x * 128;
    int tx = tid % TX;
    int ty = tid / TX;

    constexpr int NF4 = K / 4;
    for (int idx = tid; idx < 128 * NF4; idx += THREADS) {
        int r = idx / NF4, c4 = (idx % NF4) * 4;
        float4 a = *(const float4*)(A + (size_t)(m0 + r) * K + c4);
        sA[(c4    ) * SA + r] = a.x;
        sA[(c4 + 1) * SA + r] = a.y;
        sA[(c4 + 2) * SA + r] = a.z;
        sA[(c4 + 3) * SA + r] = a.w;
    }

    for (int nt = 0; nt < NTILES; nt++) {
        int n0 = nt * BN;
        __syncthreads();
        if (!TRANSB) {
            constexpr int BF4 = BN / 4;
            for (int idx = tid; idx < K * BF4; idx += THREADS) {
                int r = idx / BF4, c = (idx % BF4) * 4;
                float4 b = *(const float4*)(Bm + (size_t)r * Nout + n0 + c);
                *(float4*)&sB[r * SB + c] = b;
            }
        } else {
            constexpr int KF4 = K / 4;
            for (int idx = tid; idx < BN * KF4; idx += THREADS) {
                int n = idx / KF4, k4 = (idx % KF4) * 4;
                float4 b = *(const float4*)(Bm + (size_t)(n0 + n) * K + k4);
                sB[(k4    ) * SB + n] = b.x;
                sB[(k4 + 1) * SB + n] = b.y;
                sB[(k4 + 2) * SB + n] = b.z;
                sB[(k4 + 3) * SB + n] = b.w;
            }
        }
        __syncthreads();

        u64 acc2[4][4];
        #pragma unroll
        for (int i = 0; i < 4; i++)
            #pragma unroll
            for (int j = 0; j < 4; j++) acc2[i][j] = 0ull;

        #pragma unroll 8
        for (int kk = 0; kk < K; kk++) {
            ulonglong2 aa0 = *(const ulonglong2*)&sA[kk * SA + ty * 8];
            ulonglong2 aa1 = *(const ulonglong2*)&sA[kk * SA + ty * 8 + 4];
            float4 b = *(const float4*)&sB[kk * SB + tx * 4];
            u64 b0 = dup2(b.x), b1 = dup2(b.y), b2 = dup2(b.z), b3 = dup2(b.w);
            fma2(acc2[0][0], aa0.x, b0); fma2(acc2[0][1], aa0.x, b1);
            fma2(acc2[0][2], aa0.x, b2); fma2(acc2[0][3], aa0.x, b3);
            fma2(acc2[1][0], aa0.y, b0); fma2(acc2[1][1], aa0.y, b1);
            fma2(acc2[1][2], aa0.y, b2); fma2(acc2[1][3], aa0.y, b3);
            fma2(acc2[2][0], aa1.x, b0); fma2(acc2[2][1], aa1.x, b1);
            fma2(acc2[2][2], aa1.x, b2); fma2(acc2[2][3], aa1.x, b3);
            fma2(acc2[3][0], aa1.y, b0); fma2(acc2[3][1], aa1.y, b1);
            fma2(acc2[3][2], aa1.y, b2); fma2(acc2[3][3], aa1.y, b3);
        }

        int n = n0 + tx * 4;
        float bx = 0.f, by = 0.f, bz = 0.f, bw = 0.f;
        if (bias)  { bx += bias[n];  by += bias[n + 1];  bz += bias[n + 2];  bw += bias[n + 3]; }
        if (bias2) { bx += bias2[n]; by += bias2[n + 1]; bz += bias2[n + 2]; bw += bias2[n + 3]; }
        #pragma unroll
        for (int i2 = 0; i2 < 4; i2++) {
            float c0x, c1x, c0y, c1y, c0z, c1z, c0w, c1w;
            up2(acc2[i2][0], c0x, c1x);
            up2(acc2[i2][1], c0y, c1y);
            up2(acc2[i2][2], c0z, c1z);
            up2(acc2[i2][3], c0w, c1w);
            int m = m0 + ty * 8 + i2 * 2;
            float4 v0 = make_float4(c0x + bx, c0y + by, c0z + bz, c0w + bw);
            float4 v1 = make_float4(c1x + bx, c1y + by, c1z + bz, c1w + bw);
            if (RELU) {
                v0.x = fmaxf(v0.x, 0.f); v0.y = fmaxf(v0.y, 0.f); v0.z = fmaxf(v0.z, 0.f); v0.w = fmaxf(v0.w, 0.f);
                v1.x = fmaxf(v1.x, 0.f); v1.y = fmaxf(v1.y, 0.f); v1.z = fmaxf(v1.z, 0.f); v1.w = fmaxf(v1.w, 0.f);
            }
            *(float4*)(C + (size_t)m * Nout + n)       = v0;
            *(float4*)(C + (size_t)(m + 1) * Nout + n) = v1;
        }
    }
}

// ---------------- conv1 aggregation (8-edge unroll), normalization folded into epilogue ----------------
__global__ void agg_x_kernel(const float* __restrict__ x, float* __restrict__ out) {
    int warpId = (blockIdx.x * blockDim.x + threadIdx.x) >> 5;
    int lane = threadIdx.x & 31;
    if (warpId >= NTOT) return;
    int i = warpId;
    int beg = g_rowptr[i], end = g_rowptr[i + 1];
    float di = g_dis[i];
    float acc0 = 0.f, acc1 = 0.f, wsum_l = 0.f;

    for (int e0 = beg; e0 < end; e0 += 32) {
        int cnt = min(32, end - e0);
        int s_l = i; float w_l = 0.f;               // padding lanes: weight 0, self row (safe)
        if (lane < cnt) {
            int2 v = g_csr[e0 + lane];
            s_l = v.x;
            w_l = __int_as_float(v.y);
        }
        wsum_l += w_l;
        for (int j = 0; j < cnt; j += 8) {
            int s[8]; float w[8];
            #pragma unroll
            for (int q = 0; q < 8; q++) {
                s[q] = __shfl_sync(0xffffffffu, s_l, j + q);
                w[q] = __shfl_sync(0xffffffffu, w_l, j + q);
            }
            float a[8], b[8];
            #pragma unroll
            for (int q = 0; q < 8; q++) {
                const float* r = x + (size_t)s[q] * 64 + lane;
                a[q] = r[0]; b[q] = r[32];
            }
            #pragma unroll
            for (int q = 0; q < 8; q++) {
                acc0 += a[q] * w[q];
                acc1 += b[q] * w[q];
            }
        }
    }
    float wsum = wsum_l;
    #pragma unroll
    for (int o = 16; o; o >>= 1) wsum += __shfl_xor_sync(0xffffffffu, wsum, o);

    float di2 = di * di;
    float coef = di * wsum + di2;
    float xi0 = x[(size_t)i * 64 + lane];
    float xi1 = x[(size_t)i * 64 + lane + 32];
    out[(size_t)i * 64 + lane]      = g_rstd[lane]      * (di * acc0 + di2 * xi0 - coef * g_mean[lane]);
    out[(size_t)i * 64 + lane + 32] = g_rstd[lane + 32] * (di * acc1 + di2 * xi1 - coef * g_mean[lane + 32]);
}

// ---------------- conv2 aggregation (8-edge unroll): bias+relu epilogue ----------------
__global__ void agg_h_kernel(const float* __restrict__ hpre, const float* __restrict__ bias,
                             float* __restrict__ out) {
    int warpId = (blockIdx.x * blockDim.x + threadIdx.x) >> 5;
    int lane = threadIdx.x & 31;
    if (warpId >= NTOT) return;
    int i = warpId;
    int beg = g_rowptr[i], end = g_rowptr[i + 1];
    float di = g_dis[i];
    float acc0 = 0.f, acc1 = 0.f;

    for (int e0 = beg; e0 < end; e0 += 32) {
        int cnt = min(32, end - e0);
        int s_l = i; float w_l = 0.f;
        if (lane < cnt) {
            int2 v = g_csr[e0 + lane];
            s_l = v.x;
            w_l = __int_as_float(v.y);
        }
        for (int j = 0; j < cnt; j += 8) {
            int s[8]; float w[8];
            #pragma unroll
            for (int q = 0; q < 8; q++) {
                s[q] = __shfl_sync(0xffffffffu, s_l, j + q);
                w[q] = __shfl_sync(0xffffffffu, w_l, j + q);
            }
            float a[8], b[8];
            #pragma unroll
            for (int q = 0; q < 8; q++) {
                const float* r = hpre + (size_t)s[q] * 64 + lane;
                a[q] = r[0]; b[q] = r[32];
            }
            #pragma unroll
            for (int q = 0; q < 8; q++) {
                acc0 += a[q] * w[q];
                acc1 += b[q] * w[q];
            }
        }
    }
    float di2 = di * di;
    float s0 = hpre[(size_t)i * 64 + lane];
    float s1 = hpre[(size_t)i * 64 + lane + 32];
    out[(size_t)i * 64 + lane]      = fmaxf(acc0 * di + s0 * di2 + bias[lane],      0.f);
    out[(size_t)i * 64 + lane + 32] = fmaxf(acc1 * di + s1 * di2 + bias[lane + 32], 0.f);
}

// ---------------- LSTM (packed f32x2 weights) + fused FC head ----------------
__device__ __forceinline__ float sigm(float x) { return 1.0f / (1.0f + expf(-x)); }

__global__ __launch_bounds__(256) void lstm_head_kernel(
        const float* __restrict__ xg, const float* __restrict__ w_hh,
        const float* __restrict__ fc1_w, const float* __restrict__ fc1_b,
        const float* __restrict__ fc2_w, const float* __restrict__ fc2_b,
        float* __restrict__ out) {
    __shared__ float  h_sm[2][64];
    __shared__ __align__(16) float4 p_sm[2][4][64];
    __shared__ float  f1_sm[2][128];
    __shared__ float  lg_sm[2][3];
    int t = threadIdx.x;
    int j = t & 63, kc = t >> 6;
    int k0 = kc * 16;

    // packed weights: wIF[kk] = (w_hh[j][k], w_hh[64+j][k]), wGO[kk] = (w_hh[128+j][k], w_hh[192+j][k])
    u64 wIF[16], wGO[16];
    #pragma unroll
    for (int kk = 0; kk < 16; kk++) {
        float wi = w_hh[(size_t)(      j) * 64 + k0 + kk];
        float wf = w_hh[(size_t)( 64 + j) * 64 + k0 + kk];
        float wg = w_hh[(size_t)(128 + j) * 64 + k0 + kk];
        float wo = w_hh[(size_t)(192 + j) * 64 + k0 + kk];
        wIF[kk] = pk2(wi, wf);
        wGO[kk] = pk2(wg, wo);
    }
    int seq0 = blockIdx.x * 2;
    int bA = seq0 / NODES,       nA = seq0 % NODES;
    int bB = (seq0 + 1) / NODES, nB = (seq0 + 1) % NODES;
    int bb = kc ? bB : bA, nn = kc ? nB : nA;

    float c_state = 0.f;
    float xi = 0.f, xf = 0.f, xgg = 0.f, xo = 0.f;
    if (t < 128) {
        h_sm[kc][j] = 0.f;
        size_t row0 = ((size_t)(bb * TSTEPS) * NODES + nn) * GATES;
        xi  = xg[row0 + j];
        xf  = xg[row0 + 64 + j];
        xgg = xg[row0 + 128 + j];
        xo  = xg[row0 + 192 + j];
    }
    __syncthreads();

    for (int step = 0; step < TSTEPS; step++) {
        u64 aIF = 0ull, aGO = 0ull, bIF = 0ull, bGO = 0ull;
        #pragma unroll
        for (int kk = 0; kk < 16; kk++) {
            u64 h0d = dup2(h_sm[0][k0 + kk]);
            u64 h1d = dup2(h_sm[1][k0 + kk]);
            fma2(aIF, h0d, wIF[kk]); fma2(aGO, h0d, wGO[kk]);
            fma2(bIF, h1d, wIF[kk]); fma2(bGO, h1d, wGO[kk]);
        }
        float ai, af, ag, ao, bi, bf, bg, bo;
        up2(aIF, ai, af); up2(aGO, ag, ao);
        up2(bIF, bi, bf); up2(bGO, bg, bo);
        p_sm[0][kc][j] = make_float4(ai, af, ag, ao);
        p_sm[1][kc][j] = make_float4(bi, bf, bg, bo);
        __syncthreads();
        if (t < 128) {
            float ni = 0.f, nf = 0.f, ng = 0.f, no = 0.f;
            if (step + 1 < TSTEPS) {
                size_t rown = ((size_t)(bb * TSTEPS + step + 1) * NODES + nn) * GATES;
                ni = xg[rown + j];
                nf = xg[rown + 64 + j];
                ng = xg[rown + 128 + j];
                no = xg[rown + 192 + j];
            }
            int s = kc;
            float4 p = p_sm[s][0][j];
            float4 q = p_sm[s][1][j];
            float4 r = p_sm[s][2][j];
            float4 w = p_sm[s][3][j];
            float gi = p.x + q.x + r.x + w.x + xi;
            float gf = p.y + q.y + r.y + w.y + xf;
            float gg = p.z + q.z + r.z + w.z + xgg;
            float go = p.w + q.w + r.w + w.w + xo;
            c_state = sigm(gf) * c_state + sigm(gi) * tanhf(gg);
            h_sm[s][j] = sigm(go) * tanhf(c_state);
            xi = ni; xf = nf; xgg = ng; xo = no;
        }
        __syncthreads();
    }

    // ---- fused head: fc1+relu, fc2, softmax.  threads 0-127 -> seq0, 128-255 -> seq1 ----
    int sl = t >> 7;          // which sequence this thread serves
    int u  = t & 127;         // fc1 unit
    float acc = fc1_b[u];
    const float* w1 = fc1_w + (size_t)u * 64;
    #pragma unroll 16
    for (int k = 0; k < 64; k++) acc += h_sm[sl][k] * w1[k];
    f1_sm[sl][u] = fmaxf(acc, 0.f);
    __syncthreads();
    if (u < 3) {
        float l = fc2_b[u];
        const float* w2 = fc2_w + (size_t)u * 128;
        #pragma unroll 16
        for (int k = 0; k < 128; k++) l += f1_sm[sl][k] * w2[k];
        lg_sm[sl][u] = l;
    }
    __syncthreads();
    if (u == 0) {
        float l0 = lg_sm[sl][0], l1 = lg_sm[sl][1], l2 = lg_sm[sl][2];
        float m = fmaxf(l0, fmaxf(l1, l2));
        float e0 = expf(l0 - m), e1 = expf(l1 - m), e2 = expf(l2 - m);
        float inv = 1.0f / (e0 + e1 + e2);
        float* o = out + (size_t)(seq0 + sl) * 3;
        o[0] = e0 * inv; o[1] = e1 * inv; o[2] = e2 * inv;
    }
}

// ---------------- host launcher ----------------
static void* sym_addr(const void* sym) {
    void* p = nullptr;
    cudaGetSymbolAddress(&p, sym);
    return p;
}

extern "C" void kernel_launch(void* const* d_in, const int* in_sizes, int n_in,
                              void* d_out, int out_size) {
    const float* x        = (const float*)d_in[0];
    const float* ea       = (const float*)d_in[1];
    const float* conv1_w  = (const float*)d_in[2];
    const float* conv1_b  = (const float*)d_in[3];
    const float* conv2_w  = (const float*)d_in[4];
    const float* conv2_b  = (const float*)d_in[5];
    const float* w_ih     = (const float*)d_in[6];
    const float* w_hh     = (const float*)d_in[7];
    const float* b_ih     = (const float*)d_in[8];
    const float* b_hh     = (const float*)d_in[9];
    const float* fc1_w    = (const float*)d_in[10];
    const float* fc1_b    = (const float*)d_in[11];
    const float* fc2_w    = (const float*)d_in[12];
    const float* fc2_b    = (const float*)d_in[13];
    const int*   ei       = (const int*)d_in[14];
    float* out = (float*)d_out;

    float* aggx  = (float*)sym_addr(g_aggx);
    float* h1    = (float*)sym_addr(g_h1);
    float* h2pre = (float*)sym_addr(g_h2pre);
    float* h2    = (float*)sym_addr(g_h2);
    float* xg    = (float*)sym_addr(g_xg);

    // side stream + events, created once on the uncaptured correctness call
    static cudaStream_t sSide = nullptr;
    static cudaEvent_t  evF = nullptr, evJ = nullptr;
    if (sSide == nullptr) {
        cudaStreamCreateWithFlags(&sSide, cudaStreamNonBlocking);
        cudaEventCreateWithFlags(&evF, cudaEventDisableTiming);
        cudaEventCreateWithFlags(&evJ, cudaEventDisableTiming);
    }

    // GEMM instantiations + smem sizes
    auto g1 = gemmP_kernel<64, 96, 1, false, true >;   // aggx@W1 (+b1, relu) -> h1
    auto g2 = gemmP_kernel<96, 64, 1, false, false>;   // h1@W2           -> h2pre
    auto g3 = gemmP_kernel<64, 64, 4, true,  false>;   // h2@w_ih^T (+b)  -> xg
    size_t s1 = (size_t)(64 * 132 + 64 * 100) * 4;
    size_t s2 = (size_t)(96 * 132 + 96 * 68 ) * 4;
    size_t s3 = (size_t)(64 * 132 + 64 * 68 ) * 4;
    cudaFuncSetAttribute(g1, cudaFuncAttributeMaxDynamicSharedMemorySize, (int)s1);
    cudaFuncSetAttribute(g2, cudaFuncAttributeMaxDynamicSharedMemorySize, (int)s2);
    cudaFuncSetAttribute(g3, cudaFuncAttributeMaxDynamicSharedMemorySize, (int)s3);

    // init, then fork: column stats on side stream || edge chain on main stream
    init_kernel<<<(NTOT + 255) / 256, 256, 0, 0>>>();
    cudaEventRecord(evF, 0);
    cudaStreamWaitEvent(sSide, evF, 0);
    col_stats_kernel<<<200, 256, 0, sSide>>>(x);
    stats_finalize_kernel<<<1, 64, 0, sSide>>>();
    cudaEventRecord(evJ, sSide);

    edge_pass1_kernel<<<ETOT / 256, 256, 0, 0>>>(ei, ea);
    scan1_kernel<<<NTOT / 1024, 1024, 0, 0>>>();
    scan2_kernel<<<1, 128, 0, 0>>>();
    scan3_kernel<<<(NTOT + 255) / 256, 256, 0, 0>>>();
    edge_scatter_kernel<<<ETOT / 256, 256, 0, 0>>>(ei, ea);
    cudaStreamWaitEvent(0, evJ, 0);    // join: agg_x needs g_mean/g_rstd

    // conv1 (reordered): aggx = agg(norm(x));  h1 = relu(aggx @ W1 + b1)
    agg_x_kernel<<<NTOT / 8, 256, 0, 0>>>(x, aggx);
    g1<<<NTOT / 128, 384, s1, 0>>>(aggx, conv1_w, conv1_b, nullptr, h1);

    // conv2: h2 = relu(agg(h1 @ W2) + b2)
    g2<<<NTOT / 128, 256, s2, 0>>>(h1, conv2_w, nullptr, nullptr, h2pre);
    agg_h_kernel<<<NTOT / 8, 256, 0, 0>>>(h2pre, conv2_b, h2);

    // LSTM input projection: xg = h2 @ w_ih^T + (b_ih + b_hh)
    g3<<<NTOT / 128, 256, s3, 0>>>(h2, w_ih, b_ih, b_hh, xg);

    // recurrence + fused head
    lstm_head_kernel<<<NSEQ / 2, 256, 0, 0>>>(xg, w_hh, fc1_w, fc1_b, fc2_w, fc2_b, out);
}

// round 12
// speedup vs baseline: 1.0346x; 1.0346x over previous
#include <cuda_runtime.h>
#include <math.h>

// ---------------- problem constants ----------------
#define NTOT   102400          // B*T*NODES
#define ETOT   1638400         // edges
#define BATCH  8
#define TSTEPS 32
#define NODES  400
#define NSEQ   (BATCH*NODES)   // 3200
#define D_IN   64
#define L1F    96
#define L2F    64
#define GATES  256             // 4*64
#define FC1F   128
#define FC2F   3

typedef unsigned long long u64;

// ---------------- packed f32x2 helpers (sm_103a FFMA2 path) ----------------
__device__ __forceinline__ u64 dup2(float v) {
    u64 r; asm("mov.b64 %0, {%1, %1};" : "=l"(r) : "f"(v)); return r;
}
__device__ __forceinline__ u64 pk2(float x, float y) {
    u64 r; asm("mov.b64 %0, {%1, %2};" : "=l"(r) : "f"(x), "f"(y)); return r;
}
__device__ __forceinline__ void up2(u64 v, float& x, float& y) {
    asm("mov.b64 {%0, %1}, %2;" : "=f"(x), "=f"(y) : "l"(v));
}
__device__ __forceinline__ void fma2(u64& d, u64 a, u64 b) {
    asm("fma.rn.f32x2 %0, %1, %2, %0;" : "+l"(d) : "l"(a), "l"(b));
}

// ---------------- device scratch (static: allowed) ----------------
__device__ float g_colsum[64];
__device__ float g_colsumsq[64];
__device__ __align__(16) float g_mean[64];
__device__ __align__(16) float g_rstd[64];
__device__ int   g_counts[NTOT];
__device__ int   g_rowptr[NTOT + 1];
__device__ int   g_cursor[NTOT];
__device__ int   g_bsums[128];
__device__ float g_deg[NTOT];
__device__ float g_dis[NTOT];
__device__ __align__(16) int2  g_csr[ETOT];          // {src, float_bits(w*dis[src])}
__device__ __align__(16) float g_aggx [(size_t)NTOT * D_IN];
__device__ __align__(16) float g_h1   [(size_t)NTOT * L1F];
__device__ __align__(16) float g_h2pre[(size_t)NTOT * L2F];
__device__ __align__(16) float g_h2   [(size_t)NTOT * L2F];
__device__ __align__(16) float g_xg   [(size_t)NTOT * GATES];

// ---------------- init ----------------
__global__ void init_kernel() {
    int gid = blockIdx.x * blockDim.x + threadIdx.x;
    if (gid < NTOT) { g_counts[gid] = 0; g_deg[gid] = 1.0f; }
    if (gid < 64)   { g_colsum[gid] = 0.f; g_colsumsq[gid] = 0.f; }
}

// ---------------- column stats (mean/std, ddof=1) ----------------
__global__ void col_stats_kernel(const float* __restrict__ x) {
    __shared__ float ssum[256], ssq[256];
    int c  = threadIdx.x & 63;
    int rr = threadIdx.x >> 6;
    float s = 0.f, q = 0.f;
    for (int row = blockIdx.x * 4 + rr; row < NTOT; row += gridDim.x * 4) {
        float v = x[(size_t)row * 64 + c];
        s += v; q += v * v;
    }
    ssum[threadIdx.x] = s; ssq[threadIdx.x] = q;
    __syncthreads();
    if (threadIdx.x < 64) {
        float S = ssum[threadIdx.x] + ssum[threadIdx.x + 64] + ssum[threadIdx.x + 128] + ssum[threadIdx.x + 192];
        float Q = ssq [threadIdx.x] + ssq [threadIdx.x + 64] + ssq [threadIdx.x + 128] + ssq [threadIdx.x + 192];
        atomicAdd(&g_colsum[threadIdx.x], S);
        atomicAdd(&g_colsumsq[threadIdx.x], Q);
    }
}

__global__ void stats_finalize_kernel() {
    int c = threadIdx.x;
    if (c < 64) {
        float n = (float)NTOT;
        float mean = g_colsum[c] / n;
        float var  = (g_colsumsq[c] - n * mean * mean) / (n - 1.0f);
        g_mean[c] = mean;
        g_rstd[c] = rsqrtf(var);
    }
}

// ---------------- edge pass 1: histogram + weighted degree ----------------
__global__ void edge_pass1_kernel(const int* __restrict__ ei, const float* __restrict__ ea) {
    int e = blockIdx.x * blockDim.x + threadIdx.x;
    if (e >= ETOT) return;
    int dst = ei[ETOT + e];
    float w = fabsf(((const float2*)ea)[e].x);
    atomicAdd(&g_counts[dst], 1);
    atomicAdd(&g_deg[dst], w);
}

// ---------------- scan (exclusive) over counts ----------------
__global__ void scan1_kernel() {
    __shared__ int tmp[1024];
    int gid = blockIdx.x * 1024 + threadIdx.x;
    int v = g_counts[gid];
    tmp[threadIdx.x] = v;
    __syncthreads();
    int val = v;
    for (int off = 1; off < 1024; off <<= 1) {
        int add = (threadIdx.x >= off) ? tmp[threadIdx.x - off] : 0;
        __syncthreads();
        val += add;
        tmp[threadIdx.x] = val;
        __syncthreads();
    }
    g_rowptr[gid] = val - v;           // exclusive, local to block
    if (threadIdx.x == 1023) g_bsums[blockIdx.x] = val;
}

__global__ void scan2_kernel() {
    __shared__ int tmp[128];
    int t = threadIdx.x;
    int v = (t < NTOT / 1024) ? g_bsums[t] : 0;
    tmp[t] = v;
    __syncthreads();
    int val = v;
    for (int off = 1; off < 128; off <<= 1) {
        int add = (t >= off) ? tmp[t - off] : 0;
        __syncthreads();
        val += add;
        tmp[t] = val;
        __syncthreads();
    }
    if (t < NTOT / 1024) g_bsums[t] = val - v;   // exclusive
}

__global__ void scan3_kernel() {
    int gid = blockIdx.x * blockDim.x + threadIdx.x;
    if (gid >= NTOT) return;
    int rp = g_rowptr[gid] + g_bsums[gid >> 10];
    g_rowptr[gid] = rp;
    g_cursor[gid] = rp;
    g_dis[gid] = rsqrtf(g_deg[gid]);   // deg >= 1 always (self loop weight 1)
    if (gid == 0) g_rowptr[NTOT] = ETOT;
}

// ---------------- edge pass 2: scatter into CSR (packed int2, w pre-scaled by dis[src]) ----------------
__global__ void edge_scatter_kernel(const int* __restrict__ ei, const float* __restrict__ ea) {
    int e = blockIdx.x * blockDim.x + threadIdx.x;
    if (e >= ETOT) return;
    int dst = ei[ETOT + e];
    int src = ei[e];
    float w = fabsf(((const float2*)ea)[e].x) * g_dis[src];
    int pos = atomicAdd(&g_cursor[dst], 1);
    g_csr[pos] = make_int2(src, __float_as_int(w));
}

// ---------------- panel-resident SGEMM with packed f32x2 FMA ----------------
template<int K, int BN, int NTILES, bool TRANSB, bool RELU>
__global__ void gemmP_kernel(const float* __restrict__ A, const float* __restrict__ Bm,
                             const float* __restrict__ bias, const float* __restrict__ bias2,
                             float* __restrict__ C) {
    constexpr int Nout = BN * NTILES;
    constexpr int TX = BN / 4;
    constexpr int THREADS = TX * 16;
    constexpr int SA = 132;            // float4-aligned rows
    constexpr int SB = BN + 4;
    extern __shared__ float smem[];
    float* sA = smem;                  // [K][SA]  (k-major)
    float* sB = smem + K * SA;         // [K][SB]

    int tid = threadIdx.x;
    int m0 = blockIdx.x * 128;
    int tx = tid % TX;
    int ty = tid / TX;

    constexpr int NF4 = K / 4;
    for (int idx = tid; idx < 128 * NF4; idx += THREADS) {
        int r = idx / NF4, c4 = (idx % NF4) * 4;
        float4 a = *(const float4*)(A + (size_t)(m0 + r) * K + c4);
        sA[(c4    ) * SA + r] = a.x;
        sA[(c4 + 1) * SA + r] = a.y;
        sA[(c4 + 2) * SA + r] = a.z;
        sA[(c4 + 3) * SA + r] = a.w;
    }

    for (int nt = 0; nt < NTILES; nt++) {
        int n0 = nt * BN;
        __syncthreads();
        if (!TRANSB) {
            constexpr int BF4 = BN / 4;
            for (int idx = tid; idx < K * BF4; idx += THREADS) {
                int r = idx / BF4, c = (idx % BF4) * 4;
                float4 b = *(const float4*)(Bm + (size_t)r * Nout + n0 + c);
                *(float4*)&sB[r * SB + c] = b;
            }
        } else {
            constexpr int KF4 = K / 4;
            for (int idx = tid; idx < BN * KF4; idx += THREADS) {
                int n = idx / KF4, k4 = (idx % KF4) * 4;
                float4 b = *(const float4*)(Bm + (size_t)(n0 + n) * K + k4);
                sB[(k4    ) * SB + n] = b.x;
                sB[(k4 + 1) * SB + n] = b.y;
                sB[(k4 + 2) * SB + n] = b.z;
                sB[(k4 + 3) * SB + n] = b.w;
            }
        }
        __syncthreads();

        u64 acc2[4][4];
        #pragma unroll
        for (int i = 0; i < 4; i++)
            #pragma unroll
            for (int j = 0; j < 4; j++) acc2[i][j] = 0ull;

        #pragma unroll 8
        for (int kk = 0; kk < K; kk++) {
            ulonglong2 aa0 = *(const ulonglong2*)&sA[kk * SA + ty * 8];
            ulonglong2 aa1 = *(const ulonglong2*)&sA[kk * SA + ty * 8 + 4];
            float4 b = *(const float4*)&sB[kk * SB + tx * 4];
            u64 b0 = dup2(b.x), b1 = dup2(b.y), b2 = dup2(b.z), b3 = dup2(b.w);
            fma2(acc2[0][0], aa0.x, b0); fma2(acc2[0][1], aa0.x, b1);
            fma2(acc2[0][2], aa0.x, b2); fma2(acc2[0][3], aa0.x, b3);
            fma2(acc2[1][0], aa0.y, b0); fma2(acc2[1][1], aa0.y, b1);
            fma2(acc2[1][2], aa0.y, b2); fma2(acc2[1][3], aa0.y, b3);
            fma2(acc2[2][0], aa1.x, b0); fma2(acc2[2][1], aa1.x, b1);
            fma2(acc2[2][2], aa1.x, b2); fma2(acc2[2][3], aa1.x, b3);
            fma2(acc2[3][0], aa1.y, b0); fma2(acc2[3][1], aa1.y, b1);
            fma2(acc2[3][2], aa1.y, b2); fma2(acc2[3][3], aa1.y, b3);
        }

        int n = n0 + tx * 4;
        float bx = 0.f, by = 0.f, bz = 0.f, bw = 0.f;
        if (bias)  { bx += bias[n];  by += bias[n + 1];  bz += bias[n + 2];  bw += bias[n + 3]; }
        if (bias2) { bx += bias2[n]; by += bias2[n + 1]; bz += bias2[n + 2]; bw += bias2[n + 3]; }
        #pragma unroll
        for (int i2 = 0; i2 < 4; i2++) {
            float c0x, c1x, c0y, c1y, c0z, c1z, c0w, c1w;
            up2(acc2[i2][0], c0x, c1x);
            up2(acc2[i2][1], c0y, c1y);
            up2(acc2[i2][2], c0z, c1z);
            up2(acc2[i2][3], c0w, c1w);
            int m = m0 + ty * 8 + i2 * 2;
            float4 v0 = make_float4(c0x + bx, c0y + by, c0z + bz, c0w + bw);
            float4 v1 = make_float4(c1x + bx, c1y + by, c1z + bz, c1w + bw);
            if (RELU) {
                v0.x = fmaxf(v0.x, 0.f); v0.y = fmaxf(v0.y, 0.f); v0.z = fmaxf(v0.z, 0.f); v0.w = fmaxf(v0.w, 0.f);
                v1.x = fmaxf(v1.x, 0.f); v1.y = fmaxf(v1.y, 0.f); v1.z = fmaxf(v1.z, 0.f); v1.w = fmaxf(v1.w, 0.f);
            }
            *(float4*)(C + (size_t)m * Nout + n)       = v0;
            *(float4*)(C + (size_t)(m + 1) * Nout + n) = v1;
        }
    }
}

// ---------------- conv1 aggregation (R8/R10 form), normalization folded into epilogue ----------------
// aggx_i[c] = r[c]*( di*S[c] + di^2*x_i[c] - (di*W + di^2)*m[c] ),  S=sum wd_j*x_j, W=sum wd_j
__global__ void agg_x_kernel(const float* __restrict__ x, float* __restrict__ out) {
    int warpId = (blockIdx.x * blockDim.x + threadIdx.x) >> 5;
    int lane = threadIdx.x & 31;
    if (warpId >= NTOT) return;
    int i = warpId;
    int beg = g_rowptr[i], end = g_rowptr[i + 1];
    float di = g_dis[i];
    float acc0 = 0.f, acc1 = 0.f, wsum = 0.f;

    for (int e0 = beg; e0 < end; e0 += 32) {
        int cnt = min(32, end - e0);
        int s_l = i; float w_l = 0.f;
        if (lane < cnt) {
            int2 v = g_csr[e0 + lane];
            s_l = v.x;
            w_l = __int_as_float(v.y);
        }
        for (int j = 0; j < cnt; j += 4) {
            int   s0 = __shfl_sync(0xffffffffu, s_l, j);
            int   s1 = __shfl_sync(0xffffffffu, s_l, j + 1);
            int   s2 = __shfl_sync(0xffffffffu, s_l, j + 2);
            int   s3 = __shfl_sync(0xffffffffu, s_l, j + 3);
            float w0 = __shfl_sync(0xffffffffu, w_l, j);
            float w1 = __shfl_sync(0xffffffffu, w_l, j + 1);
            float w2 = __shfl_sync(0xffffffffu, w_l, j + 2);
            float w3 = __shfl_sync(0xffffffffu, w_l, j + 3);
            const float* r0 = x + (size_t)s0 * 64 + lane;
            const float* r1 = x + (size_t)s1 * 64 + lane;
            const float* r2 = x + (size_t)s2 * 64 + lane;
            const float* r3 = x + (size_t)s3 * 64 + lane;
            float a0 = r0[0],  a1 = r1[0],  a2 = r2[0],  a3 = r3[0];
            float b0 = r0[32], b1 = r1[32], b2 = r2[32], b3 = r3[32];
            acc0 += a0 * w0 + a1 * w1 + a2 * w2 + a3 * w3;
            acc1 += b0 * w0 + b1 * w1 + b2 * w2 + b3 * w3;
            wsum += w0 + w1 + w2 + w3;
        }
    }
    float di2 = di * di;
    float coef = di * wsum + di2;
    float xi0 = x[(size_t)i * 64 + lane];
    float xi1 = x[(size_t)i * 64 + lane + 32];
    out[(size_t)i * 64 + lane]      = g_rstd[lane]      * (di * acc0 + di2 * xi0 - coef * g_mean[lane]);
    out[(size_t)i * 64 + lane + 32] = g_rstd[lane + 32] * (di * acc1 + di2 * xi1 - coef * g_mean[lane + 32]);
}

// ---------------- conv2 aggregation (R8/R10 form): bias+relu epilogue ----------------
template<int F>
__global__ void agg_kernel(const float* __restrict__ hpre, const float* __restrict__ bias,
                           float* __restrict__ out) {
    int warpId = (blockIdx.x * blockDim.x + threadIdx.x) >> 5;
    int lane = threadIdx.x & 31;
    if (warpId >= NTOT) return;
    const int R = F / 32;
    int i = warpId;
    int beg = g_rowptr[i], end = g_rowptr[i + 1];
    float di = g_dis[i];
    float acc[R];
    #pragma unroll
    for (int r = 0; r < R; r++) acc[r] = 0.f;

    for (int e0 = beg; e0 < end; e0 += 32) {
        int cnt = min(32, end - e0);
        int s_l = i; float w_l = 0.f;
        if (lane < cnt) {
            int2 v = g_csr[e0 + lane];
            s_l = v.x;
            w_l = __int_as_float(v.y);
        }
        for (int j = 0; j < cnt; j += 4) {
            int   s0 = __shfl_sync(0xffffffffu, s_l, j);
            int   s1 = __shfl_sync(0xffffffffu, s_l, j + 1);
            int   s2 = __shfl_sync(0xffffffffu, s_l, j + 2);
            int   s3 = __shfl_sync(0xffffffffu, s_l, j + 3);
            float w0 = __shfl_sync(0xffffffffu, w_l, j);
            float w1 = __shfl_sync(0xffffffffu, w_l, j + 1);
            float w2 = __shfl_sync(0xffffffffu, w_l, j + 2);
            float w3 = __shfl_sync(0xffffffffu, w_l, j + 3);
            const float* r0 = hpre + (size_t)s0 * F + lane;
            const float* r1 = hpre + (size_t)s1 * F + lane;
            const float* r2 = hpre + (size_t)s2 * F + lane;
            const float* r3 = hpre + (size_t)s3 * F + lane;
            float v0[R], v1[R], v2[R], v3[R];
            #pragma unroll
            for (int r = 0; r < R; r++) { v0[r] = r0[32 * r]; v1[r] = r1[32 * r]; v2[r] = r2[32 * r]; v3[r] = r3[32 * r]; }
            #pragma unroll
            for (int r = 0; r < R; r++)
                acc[r] += v0[r] * w0 + v1[r] * w1 + v2[r] * w2 + v3[r] * w3;
        }
    }
    const float* self = hpre + (size_t)i * F;
    #pragma unroll
    for (int r = 0; r < R; r++) {
        float v = acc[r] * di + self[lane + 32 * r] * di * di + bias[lane + 32 * r];
        out[(size_t)i * F + lane + 32 * r] = fmaxf(v, 0.f);
    }
}

// ---------------- LSTM (packed f32x2 weights, xg prefetch) + fused FC head ----------------
__device__ __forceinline__ float sigm(float x) { return 1.0f / (1.0f + expf(-x)); }

__global__ __launch_bounds__(256) void lstm_head_kernel(
        const float* __restrict__ xg, const float* __restrict__ w_hh,
        const float* __restrict__ fc1_w, const float* __restrict__ fc1_b,
        const float* __restrict__ fc2_w, const float* __restrict__ fc2_b,
        float* __restrict__ out) {
    __shared__ float  h_sm[2][64];
    __shared__ __align__(16) float4 p_sm[2][4][64];
    __shared__ float  f1_sm[2][128];
    __shared__ float  lg_sm[2][3];
    int t = threadIdx.x;
    int j = t & 63, kc = t >> 6;
    int k0 = kc * 16;

    // packed weights: wIF[kk] = (w_hh[j][k], w_hh[64+j][k]), wGO[kk] = (w_hh[128+j][k], w_hh[192+j][k])
    u64 wIF[16], wGO[16];
    #pragma unroll
    for (int kk = 0; kk < 16; kk++) {
        float wi = w_hh[(size_t)(      j) * 64 + k0 + kk];
        float wf = w_hh[(size_t)( 64 + j) * 64 + k0 + kk];
        float wg = w_hh[(size_t)(128 + j) * 64 + k0 + kk];
        float wo = w_hh[(size_t)(192 + j) * 64 + k0 + kk];
        wIF[kk] = pk2(wi, wf);
        wGO[kk] = pk2(wg, wo);
    }
    int seq0 = blockIdx.x * 2;
    int bA = seq0 / NODES,       nA = seq0 % NODES;
    int bB = (seq0 + 1) / NODES, nB = (seq0 + 1) % NODES;
    int bb = kc ? bB : bA, nn = kc ? nB : nA;

    float c_state = 0.f;
    float xi = 0.f, xf = 0.f, xgg = 0.f, xo = 0.f;
    if (t < 128) {
        h_sm[kc][j] = 0.f;
        size_t row0 = ((size_t)(bb * TSTEPS) * NODES + nn) * GATES;
        xi  = xg[row0 + j];
        xf  = xg[row0 + 64 + j];
        xgg = xg[row0 + 128 + j];
        xo  = xg[row0 + 192 + j];
    }
    __syncthreads();

    for (int step = 0; step < TSTEPS; step++) {
        u64 aIF = 0ull, aGO = 0ull, bIF = 0ull, bGO = 0ull;
        #pragma unroll
        for (int kk = 0; kk < 16; kk++) {
            u64 h0d = dup2(h_sm[0][k0 + kk]);
            u64 h1d = dup2(h_sm[1][k0 + kk]);
            fma2(aIF, h0d, wIF[kk]); fma2(aGO, h0d, wGO[kk]);
            fma2(bIF, h1d, wIF[kk]); fma2(bGO, h1d, wGO[kk]);
        }
        float ai, af, ag, ao, bi, bf, bg, bo;
        up2(aIF, ai, af); up2(aGO, ag, ao);
        up2(bIF, bi, bf); up2(bGO, bg, bo);
        p_sm[0][kc][j] = make_float4(ai, af, ag, ao);
        p_sm[1][kc][j] = make_float4(bi, bf, bg, bo);
        __syncthreads();
        if (t < 128) {
            float ni = 0.f, nf = 0.f, ng = 0.f, no = 0.f;
            if (step + 1 < TSTEPS) {
                size_t rown = ((size_t)(bb * TSTEPS + step + 1) * NODES + nn) * GATES;
                ni = xg[rown + j];
                nf = xg[rown + 64 + j];
                ng = xg[rown + 128 + j];
                no = xg[rown + 192 + j];
            }
            int s = kc;
            float4 p = p_sm[s][0][j];
            float4 q = p_sm[s][1][j];
            float4 r = p_sm[s][2][j];
            float4 w = p_sm[s][3][j];
            float gi = p.x + q.x + r.x + w.x + xi;
            float gf = p.y + q.y + r.y + w.y + xf;
            float gg = p.z + q.z + r.z + w.z + xgg;
            float go = p.w + q.w + r.w + w.w + xo;
            c_state = sigm(gf) * c_state + sigm(gi) * tanhf(gg);
            h_sm[s][j] = sigm(go) * tanhf(c_state);
            xi = ni; xf = nf; xgg = ng; xo = no;
        }
        __syncthreads();
    }

    // ---- fused head: fc1+relu, fc2, softmax.  threads 0-127 -> seq0, 128-255 -> seq1 ----
    int sl = t >> 7;          // which sequence this thread serves
    int u  = t & 127;         // fc1 unit
    float acc = fc1_b[u];
    const float* w1 = fc1_w + (size_t)u * 64;
    #pragma unroll 16
    for (int k = 0; k < 64; k++) acc += h_sm[sl][k] * w1[k];
    f1_sm[sl][u] = fmaxf(acc, 0.f);
    __syncthreads();
    if (u < 3) {
        float l = fc2_b[u];
        const float* w2 = fc2_w + (size_t)u * 128;
        #pragma unroll 16
        for (int k = 0; k < 128; k++) l += f1_sm[sl][k] * w2[k];
        lg_sm[sl][u] = l;
    }
    __syncthreads();
    if (u == 0) {
        float l0 = lg_sm[sl][0], l1 = lg_sm[sl][1], l2 = lg_sm[sl][2];
        float m = fmaxf(l0, fmaxf(l1, l2));
        float e0 = expf(l0 - m), e1 = expf(l1 - m), e2 = expf(l2 - m);
        float inv = 1.0f / (e0 + e1 + e2);
        float* o = out + (size_t)(seq0 + sl) * 3;
        o[0] = e0 * inv; o[1] = e1 * inv; o[2] = e2 * inv;
    }
}

// ---------------- host launcher ----------------
static void* sym_addr(const void* sym) {
    void* p = nullptr;
    cudaGetSymbolAddress(&p, sym);
    return p;
}

extern "C" void kernel_launch(void* const* d_in, const int* in_sizes, int n_in,
                              void* d_out, int out_size) {
    const float* x        = (const float*)d_in[0];
    const float* ea       = (const float*)d_in[1];
    const float* conv1_w  = (const float*)d_in[2];
    const float* conv1_b  = (const float*)d_in[3];
    const float* conv2_w  = (const float*)d_in[4];
    const float* conv2_b  = (const float*)d_in[5];
    const float* w_ih     = (const float*)d_in[6];
    const float* w_hh     = (const float*)d_in[7];
    const float* b_ih     = (const float*)d_in[8];
    const float* b_hh     = (const float*)d_in[9];
    const float* fc1_w    = (const float*)d_in[10];
    const float* fc1_b    = (const float*)d_in[11];
    const float* fc2_w    = (const float*)d_in[12];
    const float* fc2_b    = (const float*)d_in[13];
    const int*   ei       = (const int*)d_in[14];
    float* out = (float*)d_out;

    float* aggx  = (float*)sym_addr(g_aggx);
    float* h1    = (float*)sym_addr(g_h1);
    float* h2pre = (float*)sym_addr(g_h2pre);
    float* h2    = (float*)sym_addr(g_h2);
    float* xg    = (float*)sym_addr(g_xg);

    // GEMM instantiations + smem sizes
    auto g1 = gemmP_kernel<64, 96, 1, false, true >;   // aggx@W1 (+b1, relu) -> h1
    auto g2 = gemmP_kernel<96, 64, 1, false, false>;   // h1@W2           -> h2pre
    auto g3 = gemmP_kernel<64, 64, 4, true,  false>;   // h2@w_ih^T (+b)  -> xg
    size_t s1 = (size_t)(64 * 132 + 64 * 100) * 4;
    size_t s2 = (size_t)(96 * 132 + 96 * 68 ) * 4;
    size_t s3 = (size_t)(64 * 132 + 64 * 68 ) * 4;
    cudaFuncSetAttribute(g1, cudaFuncAttributeMaxDynamicSharedMemorySize, (int)s1);
    cudaFuncSetAttribute(g2, cudaFuncAttributeMaxDynamicSharedMemorySize, (int)s2);
    cudaFuncSetAttribute(g3, cudaFuncAttributeMaxDynamicSharedMemorySize, (int)s3);

    // stats + graph structure (single stream, R10 order)
    init_kernel<<<(NTOT + 255) / 256, 256>>>();
    col_stats_kernel<<<200, 256>>>(x);
    stats_finalize_kernel<<<1, 64>>>();
    edge_pass1_kernel<<<ETOT / 256, 256>>>(ei, ea);
    scan1_kernel<<<NTOT / 1024, 1024>>>();
    scan2_kernel<<<1, 128>>>();
    scan3_kernel<<<(NTOT + 255) / 256, 256>>>();
    edge_scatter_kernel<<<ETOT / 256, 256>>>(ei, ea);

    // conv1 (reordered): aggx = agg(norm(x));  h1 = relu(aggx @ W1 + b1)
    agg_x_kernel<<<NTOT / 8, 256>>>(x, aggx);
    g1<<<NTOT / 128, 384, s1>>>(aggx, conv1_w, conv1_b, nullptr, h1);

    // conv2: h2 = relu(agg(h1 @ W2) + b2)
    g2<<<NTOT / 128, 256, s2>>>(h1, conv2_w, nullptr, nullptr, h2pre);
    agg_kernel<L2F><<<NTOT / 8, 256>>>(h2pre, conv2_b, h2);

    // LSTM input projection: xg = h2 @ w_ih^T + (b_ih + b_hh)
    g3<<<NTOT / 128, 256, s3>>>(h2, w_ih, b_ih, b_hh, xg);

    // recurrence + fused head (single change vs R10)
    lstm_head_kernel<<<NSEQ / 2, 256>>>(xg, w_hh, fc1_w, fc1_b, fc2_w, fc2_b, out);
}

// round 13
// speedup vs baseline: 1.0466x; 1.0116x over previous
#include <cuda_runtime.h>
#include <math.h>

// ---------------- problem constants ----------------
#define NTOT   102400          // B*T*NODES
#define ETOT   1638400         // edges
#define BATCH  8
#define TSTEPS 32
#define NODES  400
#define NSEQ   (BATCH*NODES)   // 3200
#define D_IN   64
#define L1F    96
#define L2F    64
#define GATES  256             // 4*64
#define FC1F   128
#define FC2F   3

typedef unsigned long long u64;

// ---------------- packed f32x2 helpers (sm_103a FFMA2 path) ----------------
__device__ __forceinline__ u64 dup2(float v) {
    u64 r; asm("mov.b64 %0, {%1, %1};" : "=l"(r) : "f"(v)); return r;
}
__device__ __forceinline__ u64 pk2(float x, float y) {
    u64 r; asm("mov.b64 %0, {%1, %2};" : "=l"(r) : "f"(x), "f"(y)); return r;
}
__device__ __forceinline__ void up2(u64 v, float& x, float& y) {
    asm("mov.b64 {%0, %1}, %2;" : "=f"(x), "=f"(y) : "l"(v));
}
__device__ __forceinline__ void fma2(u64& d, u64 a, u64 b) {
    asm("fma.rn.f32x2 %0, %1, %2, %0;" : "+l"(d) : "l"(a), "l"(b));
}

// ---------------- device scratch (static: allowed) ----------------
__device__ float g_colsum[64];
__device__ float g_colsumsq[64];
__device__ __align__(16) float g_mean[64];
__device__ __align__(16) float g_rstd[64];
__device__ int   g_counts[NTOT];
__device__ int   g_rowptr[NTOT + 1];
__device__ int   g_cursor[NTOT];
__device__ int   g_bsums[128];
__device__ float g_deg[NTOT];
__device__ float g_dis[NTOT];
__device__ __align__(16) int2  g_csr[ETOT];          // {src, float_bits(w*dis[src])}
__device__ __align__(16) float g_aggx [(size_t)NTOT * D_IN];
__device__ __align__(16) float g_h1   [(size_t)NTOT * L1F];
__device__ __align__(16) float g_h2pre[(size_t)NTOT * L2F];
__device__ __align__(16) float g_h2   [(size_t)NTOT * L2F];
__device__ __align__(16) float g_xg   [(size_t)NTOT * GATES];   // gate-interleaved: [row][j*4+g]
__device__ float g_hfin [(size_t)NSEQ * L2F];

// ---------------- init ----------------
__global__ void init_kernel() {
    int gid = blockIdx.x * blockDim.x + threadIdx.x;
    if (gid < NTOT) { g_counts[gid] = 0; g_deg[gid] = 1.0f; }
    if (gid < 64)   { g_colsum[gid] = 0.f; g_colsumsq[gid] = 0.f; }
}

// ---------------- column stats (mean/std, ddof=1) ----------------
__global__ void col_stats_kernel(const float* __restrict__ x) {
    __shared__ float ssum[256], ssq[256];
    int c  = threadIdx.x & 63;
    int rr = threadIdx.x >> 6;
    float s = 0.f, q = 0.f;
    for (int row = blockIdx.x * 4 + rr; row < NTOT; row += gridDim.x * 4) {
        float v = x[(size_t)row * 64 + c];
        s += v; q += v * v;
    }
    ssum[threadIdx.x] = s; ssq[threadIdx.x] = q;
    __syncthreads();
    if (threadIdx.x < 64) {
        float S = ssum[threadIdx.x] + ssum[threadIdx.x + 64] + ssum[threadIdx.x + 128] + ssum[threadIdx.x + 192];
        float Q = ssq [threadIdx.x] + ssq [threadIdx.x + 64] + ssq [threadIdx.x + 128] + ssq [threadIdx.x + 192];
        atomicAdd(&g_colsum[threadIdx.x], S);
        atomicAdd(&g_colsumsq[threadIdx.x], Q);
    }
}

__global__ void stats_finalize_kernel() {
    int c = threadIdx.x;
    if (c < 64) {
        float n = (float)NTOT;
        float mean = g_colsum[c] / n;
        float var  = (g_colsumsq[c] - n * mean * mean) / (n - 1.0f);
        g_mean[c] = mean;
        g_rstd[c] = rsqrtf(var);
    }
}

// ---------------- edge pass 1: histogram + weighted degree ----------------
__global__ void edge_pass1_kernel(const int* __restrict__ ei, const float* __restrict__ ea) {
    int e = blockIdx.x * blockDim.x + threadIdx.x;
    if (e >= ETOT) return;
    int dst = ei[ETOT + e];
    float w = fabsf(((const float2*)ea)[e].x);
    atomicAdd(&g_counts[dst], 1);
    atomicAdd(&g_deg[dst], w);
}

// ---------------- scan (exclusive) over counts ----------------
__global__ void scan1_kernel() {
    __shared__ int tmp[1024];
    int gid = blockIdx.x * 1024 + threadIdx.x;
    int v = g_counts[gid];
    tmp[threadIdx.x] = v;
    __syncthreads();
    int val = v;
    for (int off = 1; off < 1024; off <<= 1) {
        int add = (threadIdx.x >= off) ? tmp[threadIdx.x - off] : 0;
        __syncthreads();
        val += add;
        tmp[threadIdx.x] = val;
        __syncthreads();
    }
    g_rowptr[gid] = val - v;           // exclusive, local to block
    if (threadIdx.x == 1023) g_bsums[blockIdx.x] = val;
}

__global__ void scan2_kernel() {
    __shared__ int tmp[128];
    int t = threadIdx.x;
    int v = (t < NTOT / 1024) ? g_bsums[t] : 0;
    tmp[t] = v;
    __syncthreads();
    int val = v;
    for (int off = 1; off < 128; off <<= 1) {
        int add = (t >= off) ? tmp[t - off] : 0;
        __syncthreads();
        val += add;
        tmp[t] = val;
        __syncthreads();
    }
    if (t < NTOT / 1024) g_bsums[t] = val - v;   // exclusive
}

__global__ void scan3_kernel() {
    int gid = blockIdx.x * blockDim.x + threadIdx.x;
    if (gid >= NTOT) return;
    int rp = g_rowptr[gid] + g_bsums[gid >> 10];
    g_rowptr[gid] = rp;
    g_cursor[gid] = rp;
    g_dis[gid] = rsqrtf(g_deg[gid]);   // deg >= 1 always (self loop weight 1)
    if (gid == 0) g_rowptr[NTOT] = ETOT;
}

// ---------------- edge pass 2: scatter into CSR (packed int2, w pre-scaled by dis[src]) ----------------
__global__ void edge_scatter_kernel(const int* __restrict__ ei, const float* __restrict__ ea) {
    int e = blockIdx.x * blockDim.x + threadIdx.x;
    if (e >= ETOT) return;
    int dst = ei[ETOT + e];
    int src = ei[e];
    float w = fabsf(((const float2*)ea)[e].x) * g_dis[src];
    int pos = atomicAdd(&g_cursor[dst], 1);
    g_csr[pos] = make_int2(src, __float_as_int(w));
}

// ---------------- panel-resident SGEMM with packed f32x2 FMA ----------------
// GATE_ILV: output column nc corresponds to B row (nc&3)*64 + (nc>>2)   (gate-interleave
// permutation for the LSTM input projection; bias indexed with the same map).
template<int K, int BN, int NTILES, bool TRANSB, bool RELU, bool GATE_ILV>
__global__ void gemmP_kernel(const float* __restrict__ A, const float* __restrict__ Bm,
                             const float* __restrict__ bias, const float* __restrict__ bias2,
                             float* __restrict__ C) {
    constexpr int Nout = BN * NTILES;
    constexpr int TX = BN / 4;
    constexpr int THREADS = TX * 16;
    constexpr int SA = 132;            // float4-aligned rows
    constexpr int SB = BN + 4;
    extern __shared__ float smem[];
    float* sA = smem;                  // [K][SA]  (k-major)
    float* sB = smem + K * SA;         // [K][SB]

    int tid = threadIdx.x;
    int m0 = blockIdx.x * 128;
    int tx = tid % TX;
    int ty = tid / TX;

    constexpr int NF4 = K / 4;
    for (int idx = tid; idx < 128 * NF4; idx += THREADS) {
        int r = idx / NF4, c4 = (idx % NF4) * 4;
        float4 a = *(const float4*)(A + (size_t)(m0 + r) * K + c4);
        sA[(c4    ) * SA + r] = a.x;
        sA[(c4 + 1) * SA + r] = a.y;
        sA[(c4 + 2) * SA + r] = a.z;
        sA[(c4 + 3) * SA + r] = a.w;
    }

    for (int nt = 0; nt < NTILES; nt++) {
        int n0 = nt * BN;
        __syncthreads();
        if (!TRANSB) {
            constexpr int BF4 = BN / 4;
            for (int idx = tid; idx < K * BF4; idx += THREADS) {
                int r = idx / BF4, c = (idx % BF4) * 4;
                float4 b = *(const float4*)(Bm + (size_t)r * Nout + n0 + c);
                *(float4*)&sB[r * SB + c] = b;
            }
        } else {
            constexpr int KF4 = K / 4;
            for (int idx = tid; idx < BN * KF4; idx += THREADS) {
                int n = idx / KF4, k4 = (idx % KF4) * 4;
                int nc = n0 + n;
                int brow = GATE_ILV ? ((nc & 3) * 64 + (nc >> 2)) : nc;
                float4 b = *(const float4*)(Bm + (size_t)brow * K + k4);
                sB[(k4    ) * SB + n] = b.x;
                sB[(k4 + 1) * SB + n] = b.y;
                sB[(k4 + 2) * SB + n] = b.z;
                sB[(k4 + 3) * SB + n] = b.w;
            }
        }
        __syncthreads();

        u64 acc2[4][4];
        #pragma unroll
        for (int i = 0; i < 4; i++)
            #pragma unroll
            for (int j = 0; j < 4; j++) acc2[i][j] = 0ull;

        #pragma unroll 8
        for (int kk = 0; kk < K; kk++) {
            ulonglong2 aa0 = *(const ulonglong2*)&sA[kk * SA + ty * 8];
            ulonglong2 aa1 = *(const ulonglong2*)&sA[kk * SA + ty * 8 + 4];
            float4 b = *(const float4*)&sB[kk * SB + tx * 4];
            u64 b0 = dup2(b.x), b1 = dup2(b.y), b2 = dup2(b.z), b3 = dup2(b.w);
            fma2(acc2[0][0], aa0.x, b0); fma2(acc2[0][1], aa0.x, b1);
            fma2(acc2[0][2], aa0.x, b2); fma2(acc2[0][3], aa0.x, b3);
            fma2(acc2[1][0], aa0.y, b0); fma2(acc2[1][1], aa0.y, b1);
            fma2(acc2[1][2], aa0.y, b2); fma2(acc2[1][3], aa0.y, b3);
            fma2(acc2[2][0], aa1.x, b0); fma2(acc2[2][1], aa1.x, b1);
            fma2(acc2[2][2], aa1.x, b2); fma2(acc2[2][3], aa1.x, b3);
            fma2(acc2[3][0], aa1.y, b0); fma2(acc2[3][1], aa1.y, b1);
            fma2(acc2[3][2], aa1.y, b2); fma2(acc2[3][3], aa1.y, b3);
        }

        int n = n0 + tx * 4;
        float bx = 0.f, by = 0.f, bz = 0.f, bw = 0.f;
        if (GATE_ILV) {
            // columns n..n+3 are gates 0..3 of unit j = n>>2
            int jj = n >> 2;
            if (bias)  { bx += bias[jj];  by += bias[64 + jj];  bz += bias[128 + jj];  bw += bias[192 + jj]; }
            if (bias2) { bx += bias2[jj]; by += bias2[64 + jj]; bz += bias2[128 + jj]; bw += bias2[192 + jj]; }
        } else {
            if (bias)  { bx += bias[n];  by += bias[n + 1];  bz += bias[n + 2];  bw += bias[n + 3]; }
            if (bias2) { bx += bias2[n]; by += bias2[n + 1]; bz += bias2[n + 2]; bw += bias2[n + 3]; }
        }
        #pragma unroll
        for (int i2 = 0; i2 < 4; i2++) {
            float c0x, c1x, c0y, c1y, c0z, c1z, c0w, c1w;
            up2(acc2[i2][0], c0x, c1x);
            up2(acc2[i2][1], c0y, c1y);
            up2(acc2[i2][2], c0z, c1z);
            up2(acc2[i2][3], c0w, c1w);
            int m = m0 + ty * 8 + i2 * 2;
            float4 v0 = make_float4(c0x + bx, c0y + by, c0z + bz, c0w + bw);
            float4 v1 = make_float4(c1x + bx, c1y + by, c1z + bz, c1w + bw);
            if (RELU) {
                v0.x = fmaxf(v0.x, 0.f); v0.y = fmaxf(v0.y, 0.f); v0.z = fmaxf(v0.z, 0.f); v0.w = fmaxf(v0.w, 0.f);
                v1.x = fmaxf(v1.x, 0.f); v1.y = fmaxf(v1.y, 0.f); v1.z = fmaxf(v1.z, 0.f); v1.w = fmaxf(v1.w, 0.f);
            }
            *(float4*)(C + (size_t)m * Nout + n)       = v0;
            *(float4*)(C + (size_t)(m + 1) * Nout + n) = v1;
        }
    }
}

// ---------------- conv1 aggregation (R10 form), normalization folded into epilogue ----------------
__global__ void agg_x_kernel(const float* __restrict__ x, float* __restrict__ out) {
    int warpId = (blockIdx.x * blockDim.x + threadIdx.x) >> 5;
    int lane = threadIdx.x & 31;
    if (warpId >= NTOT) return;
    int i = warpId;
    int beg = g_rowptr[i], end = g_rowptr[i + 1];
    float di = g_dis[i];
    float acc0 = 0.f, acc1 = 0.f, wsum = 0.f;

    for (int e0 = beg; e0 < end; e0 += 32) {
        int cnt = min(32, end - e0);
        int s_l = i; float w_l = 0.f;
        if (lane < cnt) {
            int2 v = g_csr[e0 + lane];
            s_l = v.x;
            w_l = __int_as_float(v.y);
        }
        for (int j = 0; j < cnt; j += 4) {
            int   s0 = __shfl_sync(0xffffffffu, s_l, j);
            int   s1 = __shfl_sync(0xffffffffu, s_l, j + 1);
            int   s2 = __shfl_sync(0xffffffffu, s_l, j + 2);
            int   s3 = __shfl_sync(0xffffffffu, s_l, j + 3);
            float w0 = __shfl_sync(0xffffffffu, w_l, j);
            float w1 = __shfl_sync(0xffffffffu, w_l, j + 1);
            float w2 = __shfl_sync(0xffffffffu, w_l, j + 2);
            float w3 = __shfl_sync(0xffffffffu, w_l, j + 3);
            const float* r0 = x + (size_t)s0 * 64 + lane;
            const float* r1 = x + (size_t)s1 * 64 + lane;
            const float* r2 = x + (size_t)s2 * 64 + lane;
            const float* r3 = x + (size_t)s3 * 64 + lane;
            float a0 = r0[0],  a1 = r1[0],  a2 = r2[0],  a3 = r3[0];
            float b0 = r0[32], b1 = r1[32], b2 = r2[32], b3 = r3[32];
            acc0 += a0 * w0 + a1 * w1 + a2 * w2 + a3 * w3;
            acc1 += b0 * w0 + b1 * w1 + b2 * w2 + b3 * w3;
            wsum += w0 + w1 + w2 + w3;
        }
    }
    float di2 = di * di;
    float coef = di * wsum + di2;
    float xi0 = x[(size_t)i * 64 + lane];
    float xi1 = x[(size_t)i * 64 + lane + 32];
    out[(size_t)i * 64 + lane]      = g_rstd[lane]      * (di * acc0 + di2 * xi0 - coef * g_mean[lane]);
    out[(size_t)i * 64 + lane + 32] = g_rstd[lane + 32] * (di * acc1 + di2 * xi1 - coef * g_mean[lane + 32]);
}

// ---------------- conv2 aggregation (R10 form): bias+relu epilogue ----------------
template<int F>
__global__ void agg_kernel(const float* __restrict__ hpre, const float* __restrict__ bias,
                           float* __restrict__ out) {
    int warpId = (blockIdx.x * blockDim.x + threadIdx.x) >> 5;
    int lane = threadIdx.x & 31;
    if (warpId >= NTOT) return;
    const int R = F / 32;
    int i = warpId;
    int beg = g_rowptr[i], end = g_rowptr[i + 1];
    float di = g_dis[i];
    float acc[R];
    #pragma unroll
    for (int r = 0; r < R; r++) acc[r] = 0.f;

    for (int e0 = beg; e0 < end; e0 += 32) {
        int cnt = min(32, end - e0);
        int s_l = i; float w_l = 0.f;
        if (lane < cnt) {
            int2 v = g_csr[e0 + lane];
            s_l = v.x;
            w_l = __int_as_float(v.y);
        }
        for (int j = 0; j < cnt; j += 4) {
            int   s0 = __shfl_sync(0xffffffffu, s_l, j);
            int   s1 = __shfl_sync(0xffffffffu, s_l, j + 1);
            int   s2 = __shfl_sync(0xffffffffu, s_l, j + 2);
            int   s3 = __shfl_sync(0xffffffffu, s_l, j + 3);
            float w0 = __shfl_sync(0xffffffffu, w_l, j);
            float w1 = __shfl_sync(0xffffffffu, w_l, j + 1);
            float w2 = __shfl_sync(0xffffffffu, w_l, j + 2);
            float w3 = __shfl_sync(0xffffffffu, w_l, j + 3);
            const float* r0 = hpre + (size_t)s0 * F + lane;
            const float* r1 = hpre + (size_t)s1 * F + lane;
            const float* r2 = hpre + (size_t)s2 * F + lane;
            const float* r3 = hpre + (size_t)s3 * F + lane;
            float v0[R], v1[R], v2[R], v3[R];
            #pragma unroll
            for (int r = 0; r < R; r++) { v0[r] = r0[32 * r]; v1[r] = r1[32 * r]; v2[r] = r2[32 * r]; v3[r] = r3[32 * r]; }
            #pragma unroll
            for (int r = 0; r < R; r++)
                acc[r] += v0[r] * w0 + v1[r] * w1 + v2[r] * w2 + v3[r] * w3;
        }
    }
    const float* self = hpre + (size_t)i * F;
    #pragma unroll
    for (int r = 0; r < R; r++) {
        float v = acc[r] * di + self[lane + 32 * r] * di * di + bias[lane + 32 * r];
        out[(size_t)i * F + lane + 32 * r] = fmaxf(v, 0.f);
    }
}

// ---------------- LSTM: packed f32x2 weights + float4 gate loads (gate-interleaved xg) ----------------
__device__ __forceinline__ float sigm(float x) { return 1.0f / (1.0f + expf(-x)); }

__global__ __launch_bounds__(256) void lstm_kernel(const float* __restrict__ xg,
                                                   const float* __restrict__ w_hh,
                                                   float* __restrict__ hfinal) {
    __shared__ float  h_sm[2][64];
    __shared__ __align__(16) float4 p_sm[2][4][64];
    int t = threadIdx.x;
    int j = t & 63, kc = t >> 6;
    int k0 = kc * 16;

    // packed weights: wIF[kk] = (w_hh[j][k], w_hh[64+j][k]), wGO[kk] = (w_hh[128+j][k], w_hh[192+j][k])
    u64 wIF[16], wGO[16];
    #pragma unroll
    for (int kk = 0; kk < 16; kk++) {
        float wi = w_hh[(size_t)(      j) * 64 + k0 + kk];
        float wf = w_hh[(size_t)( 64 + j) * 64 + k0 + kk];
        float wg = w_hh[(size_t)(128 + j) * 64 + k0 + kk];
        float wo = w_hh[(size_t)(192 + j) * 64 + k0 + kk];
        wIF[kk] = pk2(wi, wf);
        wGO[kk] = pk2(wg, wo);
    }
    int seq0 = blockIdx.x * 2;
    int bA = seq0 / NODES,       nA = seq0 % NODES;
    int bB = (seq0 + 1) / NODES, nB = (seq0 + 1) % NODES;
    int bb = kc ? bB : bA, nn = kc ? nB : nA;

    float c_state = 0.f;
    float4 xv = make_float4(0.f, 0.f, 0.f, 0.f);     // (i,f,g,o) inputs for current step
    if (t < 128) {
        h_sm[kc][j] = 0.f;
        size_t row0 = ((size_t)(bb * TSTEPS) * NODES + nn) * GATES;
        xv = *(const float4*)(xg + row0 + j * 4);
    }
    __syncthreads();

    for (int step = 0; step < TSTEPS; step++) {
        u64 aIF = 0ull, aGO = 0ull, bIF = 0ull, bGO = 0ull;
        #pragma unroll
        for (int kk = 0; kk < 16; kk++) {
            u64 h0d = dup2(h_sm[0][k0 + kk]);
            u64 h1d = dup2(h_sm[1][k0 + kk]);
            fma2(aIF, h0d, wIF[kk]); fma2(aGO, h0d, wGO[kk]);
            fma2(bIF, h1d, wIF[kk]); fma2(bGO, h1d, wGO[kk]);
        }
        float ai, af, ag, ao, bi, bf, bg, bo;
        up2(aIF, ai, af); up2(aGO, ag, ao);
        up2(bIF, bi, bf); up2(bGO, bg, bo);
        p_sm[0][kc][j] = make_float4(ai, af, ag, ao);
        p_sm[1][kc][j] = make_float4(bi, bf, bg, bo);
        __syncthreads();
        if (t < 128) {
            // prefetch next step's gate inputs (one LDG.128)
            float4 nv = make_float4(0.f, 0.f, 0.f, 0.f);
            if (step + 1 < TSTEPS) {
                size_t rown = ((size_t)(bb * TSTEPS + step + 1) * NODES + nn) * GATES;
                nv = *(const float4*)(xg + rown + j * 4);
            }
            int s = kc;
            float4 p = p_sm[s][0][j];
            float4 q = p_sm[s][1][j];
            float4 r = p_sm[s][2][j];
            float4 w = p_sm[s][3][j];
            float gi = p.x + q.x + r.x + w.x + xv.x;
            float gf = p.y + q.y + r.y + w.y + xv.y;
            float gg = p.z + q.z + r.z + w.z + xv.z;
            float go = p.w + q.w + r.w + w.w + xv.w;
            c_state = sigm(gf) * c_state + sigm(gi) * tanhf(gg);
            h_sm[s][j] = sigm(go) * tanhf(c_state);
            xv = nv;
        }
        __syncthreads();
    }
    if (t < 128) hfinal[(size_t)(seq0 + kc) * 64 + j] = h_sm[kc][j];
}

// ---------------- head: fc1 + relu + fc2 + softmax (R10 form) ----------------
__global__ void head_kernel(const float* __restrict__ hfinal,
                            const float* __restrict__ fc1_w, const float* __restrict__ fc1_b,
                            const float* __restrict__ fc2_w, const float* __restrict__ fc2_b,
                            float* __restrict__ out) {
    __shared__ float h[64];
    __shared__ float f1[128];
    __shared__ float logits[3];
    int s = blockIdx.x, tid = threadIdx.x;
    if (tid < 64) h[tid] = hfinal[(size_t)s * 64 + tid];
    __syncthreads();
    float acc = fc1_b[tid];
    #pragma unroll 8
    for (int k = 0; k < 64; k++) acc += h[k] * fc1_w[(size_t)tid * 64 + k];
    f1[tid] = fmaxf(acc, 0.f);
    __syncthreads();
    if (tid < 3) {
        float l = fc2_b[tid];
        #pragma unroll 8
        for (int k = 0; k < 128; k++) l += f1[k] * fc2_w[(size_t)tid * 128 + k];
        logits[tid] = l;
    }
    __syncthreads();
    if (tid == 0) {
        float m = fmaxf(logits[0], fmaxf(logits[1], logits[2]));
        float e0 = expf(logits[0] - m), e1 = expf(logits[1] - m), e2 = expf(logits[2] - m);
        float inv = 1.0f / (e0 + e1 + e2);
        out[(size_t)s * 3 + 0] = e0 * inv;
        out[(size_t)s * 3 + 1] = e1 * inv;
        out[(size_t)s * 3 + 2] = e2 * inv;
    }
}

// ---------------- host launcher ----------------
static void* sym_addr(const void* sym) {
    void* p = nullptr;
    cudaGetSymbolAddress(&p, sym);
    return p;
}

extern "C" void kernel_launch(void* const* d_in, const int* in_sizes, int n_in,
                              void* d_out, int out_size) {
    const float* x        = (const float*)d_in[0];
    const float* ea       = (const float*)d_in[1];
    const float* conv1_w  = (const float*)d_in[2];
    const float* conv1_b  = (const float*)d_in[3];
    const float* conv2_w  = (const float*)d_in[4];
    const float* conv2_b  = (const float*)d_in[5];
    const float* w_ih     = (const float*)d_in[6];
    const float* w_hh     = (const float*)d_in[7];
    const float* b_ih     = (const float*)d_in[8];
    const float* b_hh     = (const float*)d_in[9];
    const float* fc1_w    = (const float*)d_in[10];
    const float* fc1_b    = (const float*)d_in[11];
    const float* fc2_w    = (const float*)d_in[12];
    const float* fc2_b    = (const float*)d_in[13];
    const int*   ei       = (const int*)d_in[14];
    float* out = (float*)d_out;

    float* aggx  = (float*)sym_addr(g_aggx);
    float* h1    = (float*)sym_addr(g_h1);
    float* h2pre = (float*)sym_addr(g_h2pre);
    float* h2    = (float*)sym_addr(g_h2);
    float* xg    = (float*)sym_addr(g_xg);
    float* hfin  = (float*)sym_addr(g_hfin);

    // GEMM instantiations + smem sizes
    auto g1 = gemmP_kernel<64, 96, 1, false, true,  false>;   // aggx@W1 (+b1, relu) -> h1
    auto g2 = gemmP_kernel<96, 64, 1, false, false, false>;   // h1@W2            -> h2pre
    auto g3 = gemmP_kernel<64, 64, 4, true,  false, true >;   // h2@w_ih^T (+b)   -> xg (gate-ilv)
    size_t s1 = (size_t)(64 * 132 + 64 * 100) * 4;
    size_t s2 = (size_t)(96 * 132 + 96 * 68 ) * 4;
    size_t s3 = (size_t)(64 * 132 + 64 * 68 ) * 4;
    cudaFuncSetAttribute(g1, cudaFuncAttributeMaxDynamicSharedMemorySize, (int)s1);
    cudaFuncSetAttribute(g2, cudaFuncAttributeMaxDynamicSharedMemorySize, (int)s2);
    cudaFuncSetAttribute(g3, cudaFuncAttributeMaxDynamicSharedMemorySize, (int)s3);

    // stats + graph structure (single stream, R10 order)
    init_kernel<<<(NTOT + 255) / 256, 256>>>();
    col_stats_kernel<<<200, 256>>>(x);
    stats_finalize_kernel<<<1, 64>>>();
    edge_pass1_kernel<<<ETOT / 256, 256>>>(ei, ea);
    scan1_kernel<<<NTOT / 1024, 1024>>>();
    scan2_kernel<<<1, 128>>>();
    scan3_kernel<<<(NTOT + 255) / 256, 256>>>();
    edge_scatter_kernel<<<ETOT / 256, 256>>>(ei, ea);

    // conv1 (reordered): aggx = agg(norm(x));  h1 = relu(aggx @ W1 + b1)
    agg_x_kernel<<<NTOT / 8, 256>>>(x, aggx);
    g1<<<NTOT / 128, 384, s1>>>(aggx, conv1_w, conv1_b, nullptr, h1);

    // conv2: h2 = relu(agg(h1 @ W2) + b2)
    g2<<<NTOT / 128, 256, s2>>>(h1, conv2_w, nullptr, nullptr, h2pre);
    agg_kernel<L2F><<<NTOT / 8, 256>>>(h2pre, conv2_b, h2);

    // LSTM input projection (gate-interleaved output): xg[row][j*4+g]
    g3<<<NTOT / 128, 256, s3>>>(h2, w_ih, b_ih, b_hh, xg);

    // recurrence (packed f32x2 weights, float4 gate loads)
    lstm_kernel<<<NSEQ / 2, 256>>>(xg, w_hh, hfin);

    // head
    head_kernel<<<NSEQ, 128>>>(hfin, fc1_w, fc1_b, fc2_w, fc2_b, out);
}

// round 14
// speedup vs baseline: 1.1941x; 1.1409x over previous
#include <cuda_runtime.h>
#include <math.h>

// ---------------- problem constants ----------------
#define NTOT   102400          // B*T*NODES
#define ETOT   1638400         // edges
#define BATCH  8
#define TSTEPS 32
#define NODES  400
#define NSEQ   (BATCH*NODES)   // 3200
#define D_IN   64
#define L1F    96
#define L2F    64
#define GATES  256             // 4*64
#define FC1F   128
#define FC2F   3

typedef unsigned long long u64;

// ---------------- packed f32x2 helpers (sm_103a FFMA2 path) ----------------
__device__ __forceinline__ u64 dup2(float v) {
    u64 r; asm("mov.b64 %0, {%1, %1};" : "=l"(r) : "f"(v)); return r;
}
__device__ __forceinline__ u64 pk2(float x, float y) {
    u64 r; asm("mov.b64 %0, {%1, %2};" : "=l"(r) : "f"(x), "f"(y)); return r;
}
__device__ __forceinline__ void up2(u64 v, float& x, float& y) {
    asm("mov.b64 {%0, %1}, %2;" : "=f"(x), "=f"(y) : "l"(v));
}
__device__ __forceinline__ void fma2(u64& d, u64 a, u64 b) {
    asm("fma.rn.f32x2 %0, %1, %2, %0;" : "+l"(d) : "l"(a), "l"(b));
}

// ---------------- device scratch (static: allowed) ----------------
__device__ float g_colsum[64];
__device__ float g_colsumsq[64];
__device__ __align__(16) float g_mean[64];
__device__ __align__(16) float g_rstd[64];
__device__ int   g_counts[NTOT];
__device__ int   g_rowptr[NTOT + 1];
__device__ int   g_cursor[NTOT];
__device__ int   g_bsums[128];
__device__ float g_deg[NTOT];
__device__ float g_dis[NTOT];
__device__ __align__(16) int2  g_csr[ETOT];          // {src, float_bits(w*dis[src])}
__device__ __align__(16) float g_aggx [(size_t)NTOT * D_IN];
__device__ __align__(16) float g_h1   [(size_t)NTOT * L1F];
__device__ __align__(16) float g_h2pre[(size_t)NTOT * L2F];
__device__ __align__(16) float g_h2   [(size_t)NTOT * L2F];
__device__ __align__(16) float g_xg   [(size_t)NTOT * GATES];   // gate-interleaved: [row][j*4+g]
__device__ float g_hfin [(size_t)NSEQ * L2F];

// ---------------- init ----------------
__global__ void init_kernel() {
    int gid = blockIdx.x * blockDim.x + threadIdx.x;
    if (gid < NTOT) { g_counts[gid] = 0; g_deg[gid] = 1.0f; }
    if (gid < 64)   { g_colsum[gid] = 0.f; g_colsumsq[gid] = 0.f; }
}

// ---------------- column stats (mean/std, ddof=1) ----------------
__global__ void col_stats_kernel(const float* __restrict__ x) {
    __shared__ float ssum[256], ssq[256];
    int c  = threadIdx.x & 63;
    int rr = threadIdx.x >> 6;
    float s = 0.f, q = 0.f;
    for (int row = blockIdx.x * 4 + rr; row < NTOT; row += gridDim.x * 4) {
        float v = x[(size_t)row * 64 + c];
        s += v; q += v * v;
    }
    ssum[threadIdx.x] = s; ssq[threadIdx.x] = q;
    __syncthreads();
    if (threadIdx.x < 64) {
        float S = ssum[threadIdx.x] + ssum[threadIdx.x + 64] + ssum[threadIdx.x + 128] + ssum[threadIdx.x + 192];
        float Q = ssq [threadIdx.x] + ssq [threadIdx.x + 64] + ssq [threadIdx.x + 128] + ssq [threadIdx.x + 192];
        atomicAdd(&g_colsum[threadIdx.x], S);
        atomicAdd(&g_colsumsq[threadIdx.x], Q);
    }
}

__global__ void stats_finalize_kernel() {
    int c = threadIdx.x;
    if (c < 64) {
        float n = (float)NTOT;
        float mean = g_colsum[c] / n;
        float var  = (g_colsumsq[c] - n * mean * mean) / (n - 1.0f);
        g_mean[c] = mean;
        g_rstd[c] = rsqrtf(var);
    }
}

// ---------------- edge pass 1: histogram + weighted degree ----------------
__global__ void edge_pass1_kernel(const int* __restrict__ ei, const float* __restrict__ ea) {
    int e = blockIdx.x * blockDim.x + threadIdx.x;
    if (e >= ETOT) return;
    int dst = ei[ETOT + e];
    float w = fabsf(((const float2*)ea)[e].x);
    atomicAdd(&g_counts[dst], 1);
    atomicAdd(&g_deg[dst], w);
}

// ---------------- scan (exclusive) over counts ----------------
__global__ void scan1_kernel() {
    __shared__ int tmp[1024];
    int gid = blockIdx.x * 1024 + threadIdx.x;
    int v = g_counts[gid];
    tmp[threadIdx.x] = v;
    __syncthreads();
    int val = v;
    for (int off = 1; off < 1024; off <<= 1) {
        int add = (threadIdx.x >= off) ? tmp[threadIdx.x - off] : 0;
        __syncthreads();
        val += add;
        tmp[threadIdx.x] = val;
        __syncthreads();
    }
    g_rowptr[gid] = val - v;           // exclusive, local to block
    if (threadIdx.x == 1023) g_bsums[blockIdx.x] = val;
}

__global__ void scan2_kernel() {
    __shared__ int tmp[128];
    int t = threadIdx.x;
    int v = (t < NTOT / 1024) ? g_bsums[t] : 0;
    tmp[t] = v;
    __syncthreads();
    int val = v;
    for (int off = 1; off < 128; off <<= 1) {
        int add = (t >= off) ? tmp[t - off] : 0;
        __syncthreads();
        val += add;
        tmp[t] = val;
        __syncthreads();
    }
    if (t < NTOT / 1024) g_bsums[t] = val - v;   // exclusive
}

__global__ void scan3_kernel() {
    int gid = blockIdx.x * blockDim.x + threadIdx.x;
    if (gid >= NTOT) return;
    int rp = g_rowptr[gid] + g_bsums[gid >> 10];
    g_rowptr[gid] = rp;
    g_cursor[gid] = rp;
    g_dis[gid] = rsqrtf(g_deg[gid]);   // deg >= 1 always (self loop weight 1)
    if (gid == 0) g_rowptr[NTOT] = ETOT;
}

// ---------------- edge pass 2: scatter into CSR (packed int2, w pre-scaled by dis[src]) ----------------
__global__ void edge_scatter_kernel(const int* __restrict__ ei, const float* __restrict__ ea) {
    int e = blockIdx.x * blockDim.x + threadIdx.x;
    if (e >= ETOT) return;
    int dst = ei[ETOT + e];
    int src = ei[e];
    float w = fabsf(((const float2*)ea)[e].x) * g_dis[src];
    int pos = atomicAdd(&g_cursor[dst], 1);
    g_csr[pos] = make_int2(src, __float_as_int(w));
}

// ---------------- panel-resident SGEMM with packed f32x2 FMA ----------------
// GATE_ILV: output column nc corresponds to B row (nc&3)*64 + (nc>>2)   (gate-interleave
// permutation for the LSTM input projection; bias indexed with the same map).
template<int K, int BN, int NTILES, bool TRANSB, bool RELU, bool GATE_ILV>
__global__ void gemmP_kernel(const float* __restrict__ A, const float* __restrict__ Bm,
                             const float* __restrict__ bias, const float* __restrict__ bias2,
                             float* __restrict__ C) {
    constexpr int Nout = BN * NTILES;
    constexpr int TX = BN / 4;
    constexpr int THREADS = TX * 16;
    constexpr int SA = 132;            // float4-aligned rows
    constexpr int SB = BN + 4;
    extern __shared__ float smem[];
    float* sA = smem;                  // [K][SA]  (k-major)
    float* sB = smem + K * SA;         // [K][SB]

    int tid = threadIdx.x;
    int m0 = blockIdx.x * 128;
    int tx = tid % TX;
    int ty = tid / TX;

    constexpr int NF4 = K / 4;
    for (int idx = tid; idx < 128 * NF4; idx += THREADS) {
        int r = idx / NF4, c4 = (idx % NF4) * 4;
        float4 a = *(const float4*)(A + (size_t)(m0 + r) * K + c4);
        sA[(c4    ) * SA + r] = a.x;
        sA[(c4 + 1) * SA + r] = a.y;
        sA[(c4 + 2) * SA + r] = a.z;
        sA[(c4 + 3) * SA + r] = a.w;
    }

    for (int nt = 0; nt < NTILES; nt++) {
        int n0 = nt * BN;
        __syncthreads();
        if (!TRANSB) {
            constexpr int BF4 = BN / 4;
            for (int idx = tid; idx < K * BF4; idx += THREADS) {
                int r = idx / BF4, c = (idx % BF4) * 4;
                float4 b = *(const float4*)(Bm + (size_t)r * Nout + n0 + c);
                *(float4*)&sB[r * SB + c] = b;
            }
        } else {
            constexpr int KF4 = K / 4;
            for (int idx = tid; idx < BN * KF4; idx += THREADS) {
                int n = idx / KF4, k4 = (idx % KF4) * 4;
                int nc = n0 + n;
                int brow = GATE_ILV ? ((nc & 3) * 64 + (nc >> 2)) : nc;
                float4 b = *(const float4*)(Bm + (size_t)brow * K + k4);
                sB[(k4    ) * SB + n] = b.x;
                sB[(k4 + 1) * SB + n] = b.y;
                sB[(k4 + 2) * SB + n] = b.z;
                sB[(k4 + 3) * SB + n] = b.w;
            }
        }
        __syncthreads();

        u64 acc2[4][4];
        #pragma unroll
        for (int i = 0; i < 4; i++)
            #pragma unroll
            for (int j = 0; j < 4; j++) acc2[i][j] = 0ull;

        #pragma unroll 8
        for (int kk = 0; kk < K; kk++) {
            ulonglong2 aa0 = *(const ulonglong2*)&sA[kk * SA + ty * 8];
            ulonglong2 aa1 = *(const ulonglong2*)&sA[kk * SA + ty * 8 + 4];
            float4 b = *(const float4*)&sB[kk * SB + tx * 4];
            u64 b0 = dup2(b.x), b1 = dup2(b.y), b2 = dup2(b.z), b3 = dup2(b.w);
            fma2(acc2[0][0], aa0.x, b0); fma2(acc2[0][1], aa0.x, b1);
            fma2(acc2[0][2], aa0.x, b2); fma2(acc2[0][3], aa0.x, b3);
            fma2(acc2[1][0], aa0.y, b0); fma2(acc2[1][1], aa0.y, b1);
            fma2(acc2[1][2], aa0.y, b2); fma2(acc2[1][3], aa0.y, b3);
            fma2(acc2[2][0], aa1.x, b0); fma2(acc2[2][1], aa1.x, b1);
            fma2(acc2[2][2], aa1.x, b2); fma2(acc2[2][3], aa1.x, b3);
            fma2(acc2[3][0], aa1.y, b0); fma2(acc2[3][1], aa1.y, b1);
            fma2(acc2[3][2], aa1.y, b2); fma2(acc2[3][3], aa1.y, b3);
        }

        int n = n0 + tx * 4;
        float bx = 0.f, by = 0.f, bz = 0.f, bw = 0.f;
        if (GATE_ILV) {
            int jj = n >> 2;
            if (bias)  { bx += bias[jj];  by += bias[64 + jj];  bz += bias[128 + jj];  bw += bias[192 + jj]; }
            if (bias2) { bx += bias2[jj]; by += bias2[64 + jj]; bz += bias2[128 + jj]; bw += bias2[192 + jj]; }
        } else {
            if (bias)  { bx += bias[n];  by += bias[n + 1];  bz += bias[n + 2];  bw += bias[n + 3]; }
            if (bias2) { bx += bias2[n]; by += bias2[n + 1]; bz += bias2[n + 2]; bw += bias2[n + 3]; }
        }
        #pragma unroll
        for (int i2 = 0; i2 < 4; i2++) {
            float c0x, c1x, c0y, c1y, c0z, c1z, c0w, c1w;
            up2(acc2[i2][0], c0x, c1x);
            up2(acc2[i2][1], c0y, c1y);
            up2(acc2[i2][2], c0z, c1z);
            up2(acc2[i2][3], c0w, c1w);
            int m = m0 + ty * 8 + i2 * 2;
            float4 v0 = make_float4(c0x + bx, c0y + by, c0z + bz, c0w + bw);
            float4 v1 = make_float4(c1x + bx, c1y + by, c1z + bz, c1w + bw);
            if (RELU) {
                v0.x = fmaxf(v0.x, 0.f); v0.y = fmaxf(v0.y, 0.f); v0.z = fmaxf(v0.z, 0.f); v0.w = fmaxf(v0.w, 0.f);
                v1.x = fmaxf(v1.x, 0.f); v1.y = fmaxf(v1.y, 0.f); v1.z = fmaxf(v1.z, 0.f); v1.w = fmaxf(v1.w, 0.f);
            }
            *(float4*)(C + (size_t)m * Nout + n)       = v0;
            *(float4*)(C + (size_t)(m + 1) * Nout + n) = v1;
        }
    }
}

// ---------------- conv1 aggregation (R10 form), normalization folded into epilogue ----------------
__global__ void agg_x_kernel(const float* __restrict__ x, float* __restrict__ out) {
    int warpId = (blockIdx.x * blockDim.x + threadIdx.x) >> 5;
    int lane = threadIdx.x & 31;
    if (warpId >= NTOT) return;
    int i = warpId;
    int beg = g_rowptr[i], end = g_rowptr[i + 1];
    float di = g_dis[i];
    float acc0 = 0.f, acc1 = 0.f, wsum = 0.f;

    for (int e0 = beg; e0 < end; e0 += 32) {
        int cnt = min(32, end - e0);
        int s_l = i; float w_l = 0.f;
        if (lane < cnt) {
            int2 v = g_csr[e0 + lane];
            s_l = v.x;
            w_l = __int_as_float(v.y);
        }
        for (int j = 0; j < cnt; j += 4) {
            int   s0 = __shfl_sync(0xffffffffu, s_l, j);
            int   s1 = __shfl_sync(0xffffffffu, s_l, j + 1);
            int   s2 = __shfl_sync(0xffffffffu, s_l, j + 2);
            int   s3 = __shfl_sync(0xffffffffu, s_l, j + 3);
            float w0 = __shfl_sync(0xffffffffu, w_l, j);
            float w1 = __shfl_sync(0xffffffffu, w_l, j + 1);
            float w2 = __shfl_sync(0xffffffffu, w_l, j + 2);
            float w3 = __shfl_sync(0xffffffffu, w_l, j + 3);
            const float* r0 = x + (size_t)s0 * 64 + lane;
            const float* r1 = x + (size_t)s1 * 64 + lane;
            const float* r2 = x + (size_t)s2 * 64 + lane;
            const float* r3 = x + (size_t)s3 * 64 + lane;
            float a0 = r0[0],  a1 = r1[0],  a2 = r2[0],  a3 = r3[0];
            float b0 = r0[32], b1 = r1[32], b2 = r2[32], b3 = r3[32];
            acc0 += a0 * w0 + a1 * w1 + a2 * w2 + a3 * w3;
            acc1 += b0 * w0 + b1 * w1 + b2 * w2 + b3 * w3;
            wsum += w0 + w1 + w2 + w3;
        }
    }
    float di2 = di * di;
    float coef = di * wsum + di2;
    float xi0 = x[(size_t)i * 64 + lane];
    float xi1 = x[(size_t)i * 64 + lane + 32];
    out[(size_t)i * 64 + lane]      = g_rstd[lane]      * (di * acc0 + di2 * xi0 - coef * g_mean[lane]);
    out[(size_t)i * 64 + lane + 32] = g_rstd[lane + 32] * (di * acc1 + di2 * xi1 - coef * g_mean[lane + 32]);
}

// ---------------- conv2 aggregation (R10 form): bias+relu epilogue ----------------
template<int F>
__global__ void agg_kernel(const float* __restrict__ hpre, const float* __restrict__ bias,
                           float* __restrict__ out) {
    int warpId = (blockIdx.x * blockDim.x + threadIdx.x) >> 5;
    int lane = threadIdx.x & 31;
    if (warpId >= NTOT) return;
    const int R = F / 32;
    int i = warpId;
    int beg = g_rowptr[i], end = g_rowptr[i + 1];
    float di = g_dis[i];
    float acc[R];
    #pragma unroll
    for (int r = 0; r < R; r++) acc[r] = 0.f;

    for (int e0 = beg; e0 < end; e0 += 32) {
        int cnt = min(32, end - e0);
        int s_l = i; float w_l = 0.f;
        if (lane < cnt) {
            int2 v = g_csr[e0 + lane];
            s_l = v.x;
            w_l = __int_as_float(v.y);
        }
        for (int j = 0; j < cnt; j += 4) {
            int   s0 = __shfl_sync(0xffffffffu, s_l, j);
            int   s1 = __shfl_sync(0xffffffffu, s_l, j + 1);
            int   s2 = __shfl_sync(0xffffffffu, s_l, j + 2);
            int   s3 = __shfl_sync(0xffffffffu, s_l, j + 3);
            float w0 = __shfl_sync(0xffffffffu, w_l, j);
            float w1 = __shfl_sync(0xffffffffu, w_l, j + 1);
            float w2 = __shfl_sync(0xffffffffu, w_l, j + 2);
            float w3 = __shfl_sync(0xffffffffu, w_l, j + 3);
            const float* r0 = hpre + (size_t)s0 * F + lane;
            const float* r1 = hpre + (size_t)s1 * F + lane;
            const float* r2 = hpre + (size_t)s2 * F + lane;
            const float* r3 = hpre + (size_t)s3 * F + lane;
            float v0[R], v1[R], v2[R], v3[R];
            #pragma unroll
            for (int r = 0; r < R; r++) { v0[r] = r0[32 * r]; v1[r] = r1[32 * r]; v2[r] = r2[32 * r]; v3[r] = r3[32 * r]; }
            #pragma unroll
            for (int r = 0; r < R; r++)
                acc[r] += v0[r] * w0 + v1[r] * w1 + v2[r] * w2 + v3[r] * w3;
        }
    }
    const float* self = hpre + (size_t)i * F;
    #pragma unroll
    for (int r = 0; r < R; r++) {
        float v = acc[r] * di + self[lane + 32 * r] * di * di + bias[lane + 32 * r];
        out[(size_t)i * F + lane + 32 * r] = fmaxf(v, 0.f);
    }
}

// ---------------- LSTM: 4 seqs/block, packed f32x2 weights, full-block reduce ----------------
__device__ __forceinline__ float sigm(float x) { return 1.0f / (1.0f + expf(-x)); }

__global__ __launch_bounds__(256) void lstm_kernel(const float* __restrict__ xg,
                                                   const float* __restrict__ w_hh,
                                                   float* __restrict__ hfinal) {
    __shared__ float  h_sm[4][64];
    __shared__ __align__(16) float4 p_sm[4][4][64];   // [seq][kc][j]
    int t = threadIdx.x;
    int j = t & 63, kc = t >> 6;
    int k0 = kc * 16;

    // packed weights: wIF[kk] = (w_hh[j][k], w_hh[64+j][k]), wGO[kk] = (w_hh[128+j][k], w_hh[192+j][k])
    u64 wIF[16], wGO[16];
    #pragma unroll
    for (int kk = 0; kk < 16; kk++) {
        float wi = w_hh[(size_t)(      j) * 64 + k0 + kk];
        float wf = w_hh[(size_t)( 64 + j) * 64 + k0 + kk];
        float wg = w_hh[(size_t)(128 + j) * 64 + k0 + kk];
        float wo = w_hh[(size_t)(192 + j) * 64 + k0 + kk];
        wIF[kk] = pk2(wi, wf);
        wGO[kk] = pk2(wg, wo);
    }
    int seq0 = blockIdx.x * 4;
    int myseq = seq0 + kc;                 // this thread reduces seq kc, unit j
    int bb = myseq / NODES, nn = myseq % NODES;

    float c_state = 0.f;
    h_sm[kc][j] = 0.f;                     // 256 threads exactly cover 4x64
    size_t row0 = ((size_t)(bb * TSTEPS) * NODES + nn) * GATES;
    float4 xv = *(const float4*)(xg + row0 + j * 4);
    __syncthreads();

    for (int step = 0; step < TSTEPS; step++) {
        u64 aIF[4], aGO[4];
        #pragma unroll
        for (int s = 0; s < 4; s++) { aIF[s] = 0ull; aGO[s] = 0ull; }
        #pragma unroll
        for (int kk = 0; kk < 16; kk++) {
            #pragma unroll
            for (int s = 0; s < 4; s++) {
                u64 hd = dup2(h_sm[s][k0 + kk]);
                fma2(aIF[s], hd, wIF[kk]);
                fma2(aGO[s], hd, wGO[kk]);
            }
        }
        #pragma unroll
        for (int s = 0; s < 4; s++) {
            float pi, pf, pg, po;
            up2(aIF[s], pi, pf);
            up2(aGO[s], pg, po);
            p_sm[s][kc][j] = make_float4(pi, pf, pg, po);
        }
        __syncthreads();
        {
            // prefetch next step's gate inputs (one LDG.128)
            float4 nv = make_float4(0.f, 0.f, 0.f, 0.f);
            if (step + 1 < TSTEPS) {
                size_t rown = ((size_t)(bb * TSTEPS + step + 1) * NODES + nn) * GATES;
                nv = *(const float4*)(xg + rown + j * 4);
            }
            float4 p = p_sm[kc][0][j];
            float4 q = p_sm[kc][1][j];
            float4 r = p_sm[kc][2][j];
            float4 w = p_sm[kc][3][j];
            float gi = p.x + q.x + r.x + w.x + xv.x;
            float gf = p.y + q.y + r.y + w.y + xv.y;
            float gg = p.z + q.z + r.z + w.z + xv.z;
            float go = p.w + q.w + r.w + w.w + xv.w;
            c_state = sigm(gf) * c_state + sigm(gi) * tanhf(gg);
            h_sm[kc][j] = sigm(go) * tanhf(c_state);
            xv = nv;
        }
        __syncthreads();
    }
    hfinal[(size_t)myseq * 64 + j] = h_sm[kc][j];
}

// ---------------- head: fc1 + relu + fc2 + softmax (R10 form) ----------------
__global__ void head_kernel(const float* __restrict__ hfinal,
                            const float* __restrict__ fc1_w, const float* __restrict__ fc1_b,
                            const float* __restrict__ fc2_w, const float* __restrict__ fc2_b,
                            float* __restrict__ out) {
    __shared__ float h[64];
    __shared__ float f1[128];
    __shared__ float logits[3];
    int s = blockIdx.x, tid = threadIdx.x;
    if (tid < 64) h[tid] = hfinal[(size_t)s * 64 + tid];
    __syncthreads();
    float acc = fc1_b[tid];
    #pragma unroll 8
    for (int k = 0; k < 64; k++) acc += h[k] * fc1_w[(size_t)tid * 64 + k];
    f1[tid] = fmaxf(acc, 0.f);
    __syncthreads();
    if (tid < 3) {
        float l = fc2_b[tid];
        #pragma unroll 8
        for (int k = 0; k < 128; k++) l += f1[k] * fc2_w[(size_t)tid * 128 + k];
        logits[tid] = l;
    }
    __syncthreads();
    if (tid == 0) {
        float m = fmaxf(logits[0], fmaxf(logits[1], logits[2]));
        float e0 = expf(logits[0] - m), e1 = expf(logits[1] - m), e2 = expf(logits[2] - m);
        float inv = 1.0f / (e0 + e1 + e2);
        out[(size_t)s * 3 + 0] = e0 * inv;
        out[(size_t)s * 3 + 1] = e1 * inv;
        out[(size_t)s * 3 + 2] = e2 * inv;
    }
}

// ---------------- host launcher ----------------
static void* sym_addr(const void* sym) {
    void* p = nullptr;
    cudaGetSymbolAddress(&p, sym);
    return p;
}

extern "C" void kernel_launch(void* const* d_in, const int* in_sizes, int n_in,
                              void* d_out, int out_size) {
    const float* x        = (const float*)d_in[0];
    const float* ea       = (const float*)d_in[1];
    const float* conv1_w  = (const float*)d_in[2];
    const float* conv1_b  = (const float*)d_in[3];
    const float* conv2_w  = (const float*)d_in[4];
    const float* conv2_b  = (const float*)d_in[5];
    const float* w_ih     = (const float*)d_in[6];
    const float* w_hh     = (const float*)d_in[7];
    const float* b_ih     = (const float*)d_in[8];
    const float* b_hh     = (const float*)d_in[9];
    const float* fc1_w    = (const float*)d_in[10];
    const float* fc1_b    = (const float*)d_in[11];
    const float* fc2_w    = (const float*)d_in[12];
    const float* fc2_b    = (const float*)d_in[13];
    const int*   ei       = (const int*)d_in[14];
    float* out = (float*)d_out;

    float* aggx  = (float*)sym_addr(g_aggx);
    float* h1    = (float*)sym_addr(g_h1);
    float* h2pre = (float*)sym_addr(g_h2pre);
    float* h2    = (float*)sym_addr(g_h2);
    float* xg    = (float*)sym_addr(g_xg);
    float* hfin  = (float*)sym_addr(g_hfin);

    // GEMM instantiations + smem sizes
    auto g1 = gemmP_kernel<64, 96, 1, false, true,  false>;   // aggx@W1 (+b1, relu) -> h1
    auto g2 = gemmP_kernel<96, 64, 1, false, false, false>;   // h1@W2            -> h2pre
    auto g3 = gemmP_kernel<64, 64, 4, true,  false, true >;   // h2@w_ih^T (+b)   -> xg (gate-ilv)
    size_t s1 = (size_t)(64 * 132 + 64 * 100) * 4;
    size_t s2 = (size_t)(96 * 132 + 96 * 68 ) * 4;
    size_t s3 = (size_t)(64 * 132 + 64 * 68 ) * 4;
    cudaFuncSetAttribute(g1, cudaFuncAttributeMaxDynamicSharedMemorySize, (int)s1);
    cudaFuncSetAttribute(g2, cudaFuncAttributeMaxDynamicSharedMemorySize, (int)s2);
    cudaFuncSetAttribute(g3, cudaFuncAttributeMaxDynamicSharedMemorySize, (int)s3);

    // stats + graph structure (single stream, R10 order)
    init_kernel<<<(NTOT + 255) / 256, 256>>>();
    col_stats_kernel<<<200, 256>>>(x);
    stats_finalize_kernel<<<1, 64>>>();
    edge_pass1_kernel<<<ETOT / 256, 256>>>(ei, ea);
    scan1_kernel<<<NTOT / 1024, 1024>>>();
    scan2_kernel<<<1, 128>>>();
    scan3_kernel<<<(NTOT + 255) / 256, 256>>>();
    edge_scatter_kernel<<<ETOT / 256, 256>>>(ei, ea);

    // conv1 (reordered): aggx = agg(norm(x));  h1 = relu(aggx @ W1 + b1)
    agg_x_kernel<<<NTOT / 8, 256>>>(x, aggx);
    g1<<<NTOT / 128, 384, s1>>>(aggx, conv1_w, conv1_b, nullptr, h1);

    // conv2: h2 = relu(agg(h1 @ W2) + b2)
    g2<<<NTOT / 128, 256, s2>>>(h1, conv2_w, nullptr, nullptr, h2pre);
    agg_kernel<L2F><<<NTOT / 8, 256>>>(h2pre, conv2_b, h2);

    // LSTM input projection (gate-interleaved output): xg[row][j*4+g]
    g3<<<NTOT / 128, 256, s3>>>(h2, w_ih, b_ih, b_hh, xg);

    // recurrence: 4 seqs/block, full-block reduce
    lstm_kernel<<<NSEQ / 4, 256>>>(xg, w_hh, hfin);

    // head
    head_kernel<<<NSEQ, 128>>>(hfin, fc1_w, fc1_b, fc2_w, fc2_b, out);
}

// round 15
// speedup vs baseline: 1.2560x; 1.0519x over previous
#include <cuda_runtime.h>
#include <math.h>

// ---------------- problem constants ----------------
#define NTOT   102400          // B*T*NODES
#define ETOT   1638400         // edges
#define BATCH  8
#define TSTEPS 32
#define NODES  400
#define NSEQ   (BATCH*NODES)   // 3200
#define D_IN   64
#define L1F    96
#define L2F    64
#define GATES  256             // 4*64
#define FC1F   128
#define FC2F   3

typedef unsigned long long u64;

// ---------------- packed f32x2 helpers (sm_103a FFMA2 path) ----------------
__device__ __forceinline__ u64 dup2(float v) {
    u64 r; asm("mov.b64 %0, {%1, %1};" : "=l"(r) : "f"(v)); return r;
}
__device__ __forceinline__ u64 pk2(float x, float y) {
    u64 r; asm("mov.b64 %0, {%1, %2};" : "=l"(r) : "f"(x), "f"(y)); return r;
}
__device__ __forceinline__ void up2(u64 v, float& x, float& y) {
    asm("mov.b64 {%0, %1}, %2;" : "=f"(x), "=f"(y) : "l"(v));
}
__device__ __forceinline__ void fma2(u64& d, u64 a, u64 b) {
    asm("fma.rn.f32x2 %0, %1, %2, %0;" : "+l"(d) : "l"(a), "l"(b));
}

// ---------------- device scratch (static: allowed) ----------------
__device__ float g_colsum[64];
__device__ float g_colsumsq[64];
__device__ __align__(16) float g_mean[64];
__device__ __align__(16) float g_rstd[64];
__device__ int   g_counts[NTOT];
__device__ int   g_rowptr[NTOT + 1];
__device__ int   g_cursor[NTOT];
__device__ int   g_bsums[128];
__device__ float g_deg[NTOT];
__device__ float g_dis[NTOT];
__device__ __align__(16) int2  g_csr[ETOT];          // {src, float_bits(w*dis[src])}
__device__ __align__(16) float g_aggx [(size_t)NTOT * D_IN];
__device__ __align__(16) float g_h1   [(size_t)NTOT * L1F];
__device__ __align__(16) float g_h2pre[(size_t)NTOT * L2F];
__device__ __align__(16) float g_h2   [(size_t)NTOT * L2F];
__device__ __align__(16) float g_xg   [(size_t)NTOT * GATES];   // gate-interleaved: [row][j*4+g]
__device__ float g_hfin [(size_t)NSEQ * L2F];

// ---------------- init ----------------
__global__ void init_kernel() {
    int gid = blockIdx.x * blockDim.x + threadIdx.x;
    if (gid < NTOT) { g_counts[gid] = 0; g_deg[gid] = 1.0f; }
    if (gid < 64)   { g_colsum[gid] = 0.f; g_colsumsq[gid] = 0.f; }
}

// ---------------- column stats (mean/std, ddof=1) ----------------
__global__ void col_stats_kernel(const float* __restrict__ x) {
    __shared__ float ssum[256], ssq[256];
    int c  = threadIdx.x & 63;
    int rr = threadIdx.x >> 6;
    float s = 0.f, q = 0.f;
    for (int row = blockIdx.x * 4 + rr; row < NTOT; row += gridDim.x * 4) {
        float v = x[(size_t)row * 64 + c];
        s += v; q += v * v;
    }
    ssum[threadIdx.x] = s; ssq[threadIdx.x] = q;
    __syncthreads();
    if (threadIdx.x < 64) {
        float S = ssum[threadIdx.x] + ssum[threadIdx.x + 64] + ssum[threadIdx.x + 128] + ssum[threadIdx.x + 192];
        float Q = ssq [threadIdx.x] + ssq [threadIdx.x + 64] + ssq [threadIdx.x + 128] + ssq [threadIdx.x + 192];
        atomicAdd(&g_colsum[threadIdx.x], S);
        atomicAdd(&g_colsumsq[threadIdx.x], Q);
    }
}

__global__ void stats_finalize_kernel() {
    int c = threadIdx.x;
    if (c < 64) {
        float n = (float)NTOT;
        float mean = g_colsum[c] / n;
        float var  = (g_colsumsq[c] - n * mean * mean) / (n - 1.0f);
        g_mean[c] = mean;
        g_rstd[c] = rsqrtf(var);
    }
}

// ---------------- edge pass 1: histogram + weighted degree ----------------
__global__ void edge_pass1_kernel(const int* __restrict__ ei, const float* __restrict__ ea) {
    int e = blockIdx.x * blockDim.x + threadIdx.x;
    if (e >= ETOT) return;
    int dst = ei[ETOT + e];
    float w = fabsf(((const float2*)ea)[e].x);
    atomicAdd(&g_counts[dst], 1);
    atomicAdd(&g_deg[dst], w);
}

// ---------------- scan (exclusive) over counts ----------------
__global__ void scan1_kernel() {
    __shared__ int tmp[1024];
    int gid = blockIdx.x * 1024 + threadIdx.x;
    int v = g_counts[gid];
    tmp[threadIdx.x] = v;
    __syncthreads();
    int val = v;
    for (int off = 1; off < 1024; off <<= 1) {
        int add = (threadIdx.x >= off) ? tmp[threadIdx.x - off] : 0;
        __syncthreads();
        val += add;
        tmp[threadIdx.x] = val;
        __syncthreads();
    }
    g_rowptr[gid] = val - v;           // exclusive, local to block
    if (threadIdx.x == 1023) g_bsums[blockIdx.x] = val;
}

__global__ void scan2_kernel() {
    __shared__ int tmp[128];
    int t = threadIdx.x;
    int v = (t < NTOT / 1024) ? g_bsums[t] : 0;
    tmp[t] = v;
    __syncthreads();
    int val = v;
    for (int off = 1; off < 128; off <<= 1) {
        int add = (t >= off) ? tmp[t - off] : 0;
        __syncthreads();
        val += add;
        tmp[t] = val;
        __syncthreads();
    }
    if (t < NTOT / 1024) g_bsums[t] = val - v;   // exclusive
}

__global__ void scan3_kernel() {
    int gid = blockIdx.x * blockDim.x + threadIdx.x;
    if (gid >= NTOT) return;
    int rp = g_rowptr[gid] + g_bsums[gid >> 10];
    g_rowptr[gid] = rp;
    g_cursor[gid] = rp;
    g_dis[gid] = rsqrtf(g_deg[gid]);   // deg >= 1 always (self loop weight 1)
    if (gid == 0) g_rowptr[NTOT] = ETOT;
}

// ---------------- edge pass 2: scatter into CSR (packed int2, w pre-scaled by dis[src]) ----------------
__global__ void edge_scatter_kernel(const int* __restrict__ ei, const float* __restrict__ ea) {
    int e = blockIdx.x * blockDim.x + threadIdx.x;
    if (e >= ETOT) return;
    int dst = ei[ETOT + e];
    int src = ei[e];
    float w = fabsf(((const float2*)ea)[e].x) * g_dis[src];
    int pos = atomicAdd(&g_cursor[dst], 1);
    g_csr[pos] = make_int2(src, __float_as_int(w));
}

// ---------------- panel-resident SGEMM with packed f32x2 FMA ----------------
// GATE_ILV: output column nc corresponds to B row (nc&3)*64 + (nc>>2)   (gate-interleave
// permutation for the LSTM input projection; bias indexed with the same map).
template<int K, int BN, int NTILES, bool TRANSB, bool RELU, bool GATE_ILV>
__global__ void gemmP_kernel(const float* __restrict__ A, const float* __restrict__ Bm,
                             const float* __restrict__ bias, const float* __restrict__ bias2,
                             float* __restrict__ C) {
    constexpr int Nout = BN * NTILES;
    constexpr int TX = BN / 4;
    constexpr int THREADS = TX * 16;
    constexpr int SA = 132;            // float4-aligned rows
    constexpr int SB = BN + 4;
    extern __shared__ float smem[];
    float* sA = smem;                  // [K][SA]  (k-major)
    float* sB = smem + K * SA;         // [K][SB]

    int tid = threadIdx.x;
    int m0 = blockIdx.x * 128;
    int tx = tid % TX;
    int ty = tid / TX;

    constexpr int NF4 = K / 4;
    for (int idx = tid; idx < 128 * NF4; idx += THREADS) {
        int r = idx / NF4, c4 = (idx % NF4) * 4;
        float4 a = *(const float4*)(A + (size_t)(m0 + r) * K + c4);
        sA[(c4    ) * SA + r] = a.x;
        sA[(c4 + 1) * SA + r] = a.y;
        sA[(c4 + 2) * SA + r] = a.z;
        sA[(c4 + 3) * SA + r] = a.w;
    }

    for (int nt = 0; nt < NTILES; nt++) {
        int n0 = nt * BN;
        __syncthreads();
        if (!TRANSB) {
            constexpr int BF4 = BN / 4;
            for (int idx = tid; idx < K * BF4; idx += THREADS) {
                int r = idx / BF4, c = (idx % BF4) * 4;
                float4 b = *(const float4*)(Bm + (size_t)r * Nout + n0 + c);
                *(float4*)&sB[r * SB + c] = b;
            }
        } else {
            constexpr int KF4 = K / 4;
            for (int idx = tid; idx < BN * KF4; idx += THREADS) {
                int n = idx / KF4, k4 = (idx % KF4) * 4;
                int nc = n0 + n;
                int brow = GATE_ILV ? ((nc & 3) * 64 + (nc >> 2)) : nc;
                float4 b = *(const float4*)(Bm + (size_t)brow * K + k4);
                sB[(k4    ) * SB + n] = b.x;
                sB[(k4 + 1) * SB + n] = b.y;
                sB[(k4 + 2) * SB + n] = b.z;
                sB[(k4 + 3) * SB + n] = b.w;
            }
        }
        __syncthreads();

        u64 acc2[4][4];
        #pragma unroll
        for (int i = 0; i < 4; i++)
            #pragma unroll
            for (int j = 0; j < 4; j++) acc2[i][j] = 0ull;

        #pragma unroll 8
        for (int kk = 0; kk < K; kk++) {
            ulonglong2 aa0 = *(const ulonglong2*)&sA[kk * SA + ty * 8];
            ulonglong2 aa1 = *(const ulonglong2*)&sA[kk * SA + ty * 8 + 4];
            float4 b = *(const float4*)&sB[kk * SB + tx * 4];
            u64 b0 = dup2(b.x), b1 = dup2(b.y), b2 = dup2(b.z), b3 = dup2(b.w);
            fma2(acc2[0][0], aa0.x, b0); fma2(acc2[0][1], aa0.x, b1);
            fma2(acc2[0][2], aa0.x, b2); fma2(acc2[0][3], aa0.x, b3);
            fma2(acc2[1][0], aa0.y, b0); fma2(acc2[1][1], aa0.y, b1);
            fma2(acc2[1][2], aa0.y, b2); fma2(acc2[1][3], aa0.y, b3);
            fma2(acc2[2][0], aa1.x, b0); fma2(acc2[2][1], aa1.x, b1);
            fma2(acc2[2][2], aa1.x, b2); fma2(acc2[2][3], aa1.x, b3);
            fma2(acc2[3][0], aa1.y, b0); fma2(acc2[3][1], aa1.y, b1);
            fma2(acc2[3][2], aa1.y, b2); fma2(acc2[3][3], aa1.y, b3);
        }

        int n = n0 + tx * 4;
        float bx = 0.f, by = 0.f, bz = 0.f, bw = 0.f;
        if (GATE_ILV) {
            int jj = n >> 2;
            if (bias)  { bx += bias[jj];  by += bias[64 + jj];  bz += bias[128 + jj];  bw += bias[192 + jj]; }
            if (bias2) { bx += bias2[jj]; by += bias2[64 + jj]; bz += bias2[128 + jj]; bw += bias2[192 + jj]; }
        } else {
            if (bias)  { bx += bias[n];  by += bias[n + 1];  bz += bias[n + 2];  bw += bias[n + 3]; }
            if (bias2) { bx += bias2[n]; by += bias2[n + 1]; bz += bias2[n + 2]; bw += bias2[n + 3]; }
        }
        #pragma unroll
        for (int i2 = 0; i2 < 4; i2++) {
            float c0x, c1x, c0y, c1y, c0z, c1z, c0w, c1w;
            up2(acc2[i2][0], c0x, c1x);
            up2(acc2[i2][1], c0y, c1y);
            up2(acc2[i2][2], c0z, c1z);
            up2(acc2[i2][3], c0w, c1w);
            int m = m0 + ty * 8 + i2 * 2;
            float4 v0 = make_float4(c0x + bx, c0y + by, c0z + bz, c0w + bw);
            float4 v1 = make_float4(c1x + bx, c1y + by, c1z + bz, c1w + bw);
            if (RELU) {
                v0.x = fmaxf(v0.x, 0.f); v0.y = fmaxf(v0.y, 0.f); v0.z = fmaxf(v0.z, 0.f); v0.w = fmaxf(v0.w, 0.f);
                v1.x = fmaxf(v1.x, 0.f); v1.y = fmaxf(v1.y, 0.f); v1.z = fmaxf(v1.z, 0.f); v1.w = fmaxf(v1.w, 0.f);
            }
            *(float4*)(C + (size_t)m * Nout + n)       = v0;
            *(float4*)(C + (size_t)(m + 1) * Nout + n) = v1;
        }
    }
}

// ---------------- conv1 aggregation (float2 lanes), normalization folded into epilogue ----------------
// lane covers features 2*lane, 2*lane+1.  One LDG.64 per edge per lane.
__global__ void agg_x_kernel(const float* __restrict__ x, float* __restrict__ out) {
    int warpId = (blockIdx.x * blockDim.x + threadIdx.x) >> 5;
    int lane = threadIdx.x & 31;
    if (warpId >= NTOT) return;
    int i = warpId;
    int beg = g_rowptr[i], end = g_rowptr[i + 1];
    float di = g_dis[i];
    float accx = 0.f, accy = 0.f, wsum = 0.f;

    for (int e0 = beg; e0 < end; e0 += 32) {
        int cnt = min(32, end - e0);
        int s_l = i; float w_l = 0.f;
        if (lane < cnt) {
            int2 v = g_csr[e0 + lane];
            s_l = v.x;
            w_l = __int_as_float(v.y);
        }
        for (int j = 0; j < cnt; j += 4) {
            int   s0 = __shfl_sync(0xffffffffu, s_l, j);
            int   s1 = __shfl_sync(0xffffffffu, s_l, j + 1);
            int   s2 = __shfl_sync(0xffffffffu, s_l, j + 2);
            int   s3 = __shfl_sync(0xffffffffu, s_l, j + 3);
            float w0 = __shfl_sync(0xffffffffu, w_l, j);
            float w1 = __shfl_sync(0xffffffffu, w_l, j + 1);
            float w2 = __shfl_sync(0xffffffffu, w_l, j + 2);
            float w3 = __shfl_sync(0xffffffffu, w_l, j + 3);
            float2 a0 = ((const float2*)(x + (size_t)s0 * 64))[lane];
            float2 a1 = ((const float2*)(x + (size_t)s1 * 64))[lane];
            float2 a2 = ((const float2*)(x + (size_t)s2 * 64))[lane];
            float2 a3 = ((const float2*)(x + (size_t)s3 * 64))[lane];
            accx += a0.x * w0 + a1.x * w1 + a2.x * w2 + a3.x * w3;
            accy += a0.y * w0 + a1.y * w1 + a2.y * w2 + a3.y * w3;
            wsum += w0 + w1 + w2 + w3;
        }
    }
    float di2 = di * di;
    float coef = di * wsum + di2;
    float2 m  = ((const float2*)g_mean)[lane];
    float2 r  = ((const float2*)g_rstd)[lane];
    float2 xi = ((const float2*)(x + (size_t)i * 64))[lane];
    float2 o;
    o.x = r.x * (di * accx + di2 * xi.x - coef * m.x);
    o.y = r.y * (di * accy + di2 * xi.y - coef * m.y);
    ((float2*)(out + (size_t)i * 64))[lane] = o;
}

// ---------------- conv2 aggregation (float2 lanes): bias+relu epilogue ----------------
__global__ void agg_h_kernel(const float* __restrict__ hpre, const float* __restrict__ bias,
                             float* __restrict__ out) {
    int warpId = (blockIdx.x * blockDim.x + threadIdx.x) >> 5;
    int lane = threadIdx.x & 31;
    if (warpId >= NTOT) return;
    int i = warpId;
    int beg = g_rowptr[i], end = g_rowptr[i + 1];
    float di = g_dis[i];
    float accx = 0.f, accy = 0.f;

    for (int e0 = beg; e0 < end; e0 += 32) {
        int cnt = min(32, end - e0);
        int s_l = i; float w_l = 0.f;
        if (lane < cnt) {
            int2 v = g_csr[e0 + lane];
            s_l = v.x;
            w_l = __int_as_float(v.y);
        }
        for (int j = 0; j < cnt; j += 4) {
            int   s0 = __shfl_sync(0xffffffffu, s_l, j);
            int   s1 = __shfl_sync(0xffffffffu, s_l, j + 1);
            int   s2 = __shfl_sync(0xffffffffu, s_l, j + 2);
            int   s3 = __shfl_sync(0xffffffffu, s_l, j + 3);
            float w0 = __shfl_sync(0xffffffffu, w_l, j);
            float w1 = __shfl_sync(0xffffffffu, w_l, j + 1);
            float w2 = __shfl_sync(0xffffffffu, w_l, j + 2);
            float w3 = __shfl_sync(0xffffffffu, w_l, j + 3);
            float2 a0 = ((const float2*)(hpre + (size_t)s0 * 64))[lane];
            float2 a1 = ((const float2*)(hpre + (size_t)s1 * 64))[lane];
            float2 a2 = ((const float2*)(hpre + (size_t)s2 * 64))[lane];
            float2 a3 = ((const float2*)(hpre + (size_t)s3 * 64))[lane];
            accx += a0.x * w0 + a1.x * w1 + a2.x * w2 + a3.x * w3;
            accy += a0.y * w0 + a1.y * w1 + a2.y * w2 + a3.y * w3;
        }
    }
    float di2 = di * di;
    float2 self = ((const float2*)(hpre + (size_t)i * 64))[lane];
    float2 b    = ((const float2*)bias)[lane];
    float2 o;
    o.x = fmaxf(accx * di + self.x * di2 + b.x, 0.f);
    o.y = fmaxf(accy * di + self.y * di2 + b.y, 0.f);
    ((float2*)(out + (size_t)i * 64))[lane] = o;
}

// ---------------- LSTM: 4 seqs/block, packed f32x2 weights, full-block reduce ----------------
__device__ __forceinline__ float sigm(float x) { return 1.0f / (1.0f + expf(-x)); }

__global__ __launch_bounds__(256) void lstm_kernel(const float* __restrict__ xg,
                                                   const float* __restrict__ w_hh,
                                                   float* __restrict__ hfinal) {
    __shared__ float  h_sm[4][64];
    __shared__ __align__(16) float4 p_sm[4][4][64];   // [seq][kc][j]
    int t = threadIdx.x;
    int j = t & 63, kc = t >> 6;
    int k0 = kc * 16;

    // packed weights: wIF[kk] = (w_hh[j][k], w_hh[64+j][k]), wGO[kk] = (w_hh[128+j][k], w_hh[192+j][k])
    u64 wIF[16], wGO[16];
    #pragma unroll
    for (int kk = 0; kk < 16; kk++) {
        float wi = w_hh[(size_t)(      j) * 64 + k0 + kk];
        float wf = w_hh[(size_t)( 64 + j) * 64 + k0 + kk];
        float wg = w_hh[(size_t)(128 + j) * 64 + k0 + kk];
        float wo = w_hh[(size_t)(192 + j) * 64 + k0 + kk];
        wIF[kk] = pk2(wi, wf);
        wGO[kk] = pk2(wg, wo);
    }
    int seq0 = blockIdx.x * 4;
    int myseq = seq0 + kc;                 // this thread reduces seq kc, unit j
    int bb = myseq / NODES, nn = myseq % NODES;

    float c_state = 0.f;
    h_sm[kc][j] = 0.f;                     // 256 threads exactly cover 4x64
    size_t row0 = ((size_t)(bb * TSTEPS) * NODES + nn) * GATES;
    float4 xv = *(const float4*)(xg + row0 + j * 4);
    __syncthreads();

    for (int step = 0; step < TSTEPS; step++) {
        u64 aIF[4], aGO[4];
        #pragma unroll
        for (int s = 0; s < 4; s++) { aIF[s] = 0ull; aGO[s] = 0ull; }
        #pragma unroll
        for (int kk = 0; kk < 16; kk++) {
            #pragma unroll
            for (int s = 0; s < 4; s++) {
                u64 hd = dup2(h_sm[s][k0 + kk]);
                fma2(aIF[s], hd, wIF[kk]);
                fma2(aGO[s], hd, wGO[kk]);
            }
        }
        #pragma unroll
        for (int s = 0; s < 4; s++) {
            float pi, pf, pg, po;
            up2(aIF[s], pi, pf);
            up2(aGO[s], pg, po);
            p_sm[s][kc][j] = make_float4(pi, pf, pg, po);
        }
        __syncthreads();
        {
            // prefetch next step's gate inputs (one LDG.128)
            float4 nv = make_float4(0.f, 0.f, 0.f, 0.f);
            if (step + 1 < TSTEPS) {
                size_t rown = ((size_t)(bb * TSTEPS + step + 1) * NODES + nn) * GATES;
                nv = *(const float4*)(xg + rown + j * 4);
            }
            float4 p = p_sm[kc][0][j];
            float4 q = p_sm[kc][1][j];
            float4 r = p_sm[kc][2][j];
            float4 w = p_sm[kc][3][j];
            float gi = p.x + q.x + r.x + w.x + xv.x;
            float gf = p.y + q.y + r.y + w.y + xv.y;
            float gg = p.z + q.z + r.z + w.z + xv.z;
            float go = p.w + q.w + r.w + w.w + xv.w;
            c_state = sigm(gf) * c_state + sigm(gi) * tanhf(gg);
            h_sm[kc][j] = sigm(go) * tanhf(c_state);
            xv = nv;
        }
        __syncthreads();
    }
    hfinal[(size_t)myseq * 64 + j] = h_sm[kc][j];
}

// ---------------- head: fc1 + relu + fc2 + softmax ----------------
__global__ void head_kernel(const float* __restrict__ hfinal,
                            const float* __restrict__ fc1_w, const float* __restrict__ fc1_b,
                            const float* __restrict__ fc2_w, const float* __restrict__ fc2_b,
                            float* __restrict__ out) {
    __shared__ float h[64];
    __shared__ float f1[128];
    __shared__ float logits[3];
    int s = blockIdx.x, tid = threadIdx.x;
    if (tid < 64) h[tid] = hfinal[(size_t)s * 64 + tid];
    __syncthreads();
    float acc = fc1_b[tid];
    #pragma unroll 8
    for (int k = 0; k < 64; k++) acc += h[k] * fc1_w[(size_t)tid * 64 + k];
    f1[tid] = fmaxf(acc, 0.f);
    __syncthreads();
    if (tid < 3) {
        float l = fc2_b[tid];
        #pragma unroll 8
        for (int k = 0; k < 128; k++) l += f1[k] * fc2_w[(size_t)tid * 128 + k];
        logits[tid] = l;
    }
    __syncthreads();
    if (tid == 0) {
        float m = fmaxf(logits[0], fmaxf(logits[1], logits[2]));
        float e0 = expf(logits[0] - m), e1 = expf(logits[1] - m), e2 = expf(logits[2] - m);
        float inv = 1.0f / (e0 + e1 + e2);
        out[(size_t)s * 3 + 0] = e0 * inv;
        out[(size_t)s * 3 + 1] = e1 * inv;
        out[(size_t)s * 3 + 2] = e2 * inv;
    }
}

// ---------------- host launcher ----------------
static void* sym_addr(const void* sym) {
    void* p = nullptr;
    cudaGetSymbolAddress(&p, sym);
    return p;
}

extern "C" void kernel_launch(void* const* d_in, const int* in_sizes, int n_in,
                              void* d_out, int out_size) {
    const float* x        = (const float*)d_in[0];
    const float* ea       = (const float*)d_in[1];
    const float* conv1_w  = (const float*)d_in[2];
    const float* conv1_b  = (const float*)d_in[3];
    const float* conv2_w  = (const float*)d_in[4];
    const float* conv2_b  = (const float*)d_in[5];
    const float* w_ih     = (const float*)d_in[6];
    const float* w_hh     = (const float*)d_in[7];
    const float* b_ih     = (const float*)d_in[8];
    const float* b_hh     = (const float*)d_in[9];
    const float* fc1_w    = (const float*)d_in[10];
    const float* fc1_b    = (const float*)d_in[11];
    const float* fc2_w    = (const float*)d_in[12];
    const float* fc2_b    = (const float*)d_in[13];
    const int*   ei       = (const int*)d_in[14];
    float* out = (float*)d_out;

    float* aggx  = (float*)sym_addr(g_aggx);
    float* h1    = (float*)sym_addr(g_h1);
    float* h2pre = (float*)sym_addr(g_h2pre);
    float* h2    = (float*)sym_addr(g_h2);
    float* xg    = (float*)sym_addr(g_xg);
    float* hfin  = (float*)sym_addr(g_hfin);

    // GEMM instantiations + smem sizes
    auto g1 = gemmP_kernel<64, 96, 1, false, true,  false>;   // aggx@W1 (+b1, relu) -> h1
    auto g2 = gemmP_kernel<96, 64, 1, false, false, false>;   // h1@W2            -> h2pre
    auto g3 = gemmP_kernel<64, 64, 4, true,  false, true >;   // h2@w_ih^T (+b)   -> xg (gate-ilv)
    size_t s1 = (size_t)(64 * 132 + 64 * 100) * 4;
    size_t s2 = (size_t)(96 * 132 + 96 * 68 ) * 4;
    size_t s3 = (size_t)(64 * 132 + 64 * 68 ) * 4;
    cudaFuncSetAttribute(g1, cudaFuncAttributeMaxDynamicSharedMemorySize, (int)s1);
    cudaFuncSetAttribute(g2, cudaFuncAttributeMaxDynamicSharedMemorySize, (int)s2);
    cudaFuncSetAttribute(g3, cudaFuncAttributeMaxDynamicSharedMemorySize, (int)s3);

    // stats + graph structure (single stream)
    init_kernel<<<(NTOT + 255) / 256, 256>>>();
    col_stats_kernel<<<1600, 256>>>(x);
    stats_finalize_kernel<<<1, 64>>>();
    edge_pass1_kernel<<<ETOT / 256, 256>>>(ei, ea);
    scan1_kernel<<<NTOT / 1024, 1024>>>();
    scan2_kernel<<<1, 128>>>();
    scan3_kernel<<<(NTOT + 255) / 256, 256>>>();
    edge_scatter_kernel<<<ETOT / 256, 256>>>(ei, ea);

    // conv1 (reordered): aggx = agg(norm(x));  h1 = relu(aggx @ W1 + b1)
    agg_x_kernel<<<NTOT / 8, 256>>>(x, aggx);
    g1<<<NTOT / 128, 384, s1>>>(aggx, conv1_w, conv1_b, nullptr, h1);

    // conv2: h2 = relu(agg(h1 @ W2) + b2)
    g2<<<NTOT / 128, 256, s2>>>(h1, conv2_w, nullptr, nullptr, h2pre);
    agg_h_kernel<<<NTOT / 8, 256>>>(h2pre, conv2_b, h2);

    // LSTM input projection (gate-interleaved output): xg[row][j*4+g]
    g3<<<NTOT / 128, 256, s3>>>(h2, w_ih, b_ih, b_hh, xg);

    // recurrence: 4 seqs/block, full-block reduce
    lstm_kernel<<<NSEQ / 4, 256>>>(xg, w_hh, hfin);

    // head
    head_kernel<<<NSEQ, 128>>>(hfin, fc1_w, fc1_b, fc2_w, fc2_b, out);
}

// round 16
// speedup vs baseline: 1.2877x; 1.0252x over previous
#include <cuda_runtime.h>
#include <math.h>

// ---------------- problem constants ----------------
#define NTOT   102400          // B*T*NODES
#define ETOT   1638400         // edges
#define BATCH  8
#define TSTEPS 32
#define NODES  400
#define NSEQ   (BATCH*NODES)   // 3200
#define D_IN   64
#define L1F    96
#define L2F    64
#define GATES  256             // 4*64
#define FC1F   128
#define FC2F   3

#define EDGE_BLOCKS  (ETOT / 256)   // 6400
#define STAT_BLOCKS  1600

typedef unsigned long long u64;

// ---------------- packed f32x2 helpers (sm_103a FFMA2 path) ----------------
__device__ __forceinline__ u64 dup2(float v) {
    u64 r; asm("mov.b64 %0, {%1, %1};" : "=l"(r) : "f"(v)); return r;
}
__device__ __forceinline__ u64 pk2(float x, float y) {
    u64 r; asm("mov.b64 %0, {%1, %2};" : "=l"(r) : "f"(x), "f"(y)); return r;
}
__device__ __forceinline__ void up2(u64 v, float& x, float& y) {
    asm("mov.b64 {%0, %1}, %2;" : "=f"(x), "=f"(y) : "l"(v));
}
__device__ __forceinline__ void fma2(u64& d, u64 a, u64 b) {
    asm("fma.rn.f32x2 %0, %1, %2, %0;" : "+l"(d) : "l"(a), "l"(b));
}

// ---------------- device scratch (static: allowed) ----------------
__device__ float g_colsum[64];
__device__ float g_colsumsq[64];
__device__ __align__(16) float g_mean[64];
__device__ __align__(16) float g_rstd[64];
__device__ int   g_counts[NTOT];
__device__ int   g_rowptr[NTOT + 1];
__device__ int   g_cursor[NTOT];
__device__ int   g_bsums[128];
__device__ float g_deg[NTOT];
__device__ float g_dis[NTOT];
__device__ __align__(16) int2  g_csr[ETOT];          // {src, float_bits(w*dis[src])}
__device__ __align__(16) float g_aggx [(size_t)NTOT * D_IN];
__device__ __align__(16) float g_h1   [(size_t)NTOT * L1F];
__device__ __align__(16) float g_h2pre[(size_t)NTOT * L2F];
__device__ __align__(16) float g_h2   [(size_t)NTOT * L2F];
__device__ __align__(16) float g_xg   [(size_t)NTOT * GATES];   // gate-interleaved: [row][j*4+g]
__device__ float g_hfin [(size_t)NSEQ * L2F];

// ---------------- init ----------------
__global__ void init_kernel() {
    int gid = blockIdx.x * blockDim.x + threadIdx.x;
    if (gid < NTOT) { g_counts[gid] = 0; g_deg[gid] = 1.0f; }
    if (gid < 64)   { g_colsum[gid] = 0.f; g_colsumsq[gid] = 0.f; }
}

// ---------------- fused: edge histogram/degree (blocks 0..6399) + column stats (6400..7999) ----------------
__global__ void stats_edge_kernel(const float* __restrict__ x,
                                  const int* __restrict__ ei, const float* __restrict__ ea) {
    if (blockIdx.x < EDGE_BLOCKS) {
        int e = blockIdx.x * 256 + threadIdx.x;
        int dst = ei[ETOT + e];
        float w = fabsf(((const float2*)ea)[e].x);
        atomicAdd(&g_counts[dst], 1);
        atomicAdd(&g_deg[dst], w);
    } else {
        __shared__ float ssum[256], ssq[256];
        int bs = blockIdx.x - EDGE_BLOCKS;           // 0..STAT_BLOCKS-1
        int c  = threadIdx.x & 63;
        int rr = threadIdx.x >> 6;
        float s = 0.f, q = 0.f;
        for (int row = bs * 4 + rr; row < NTOT; row += STAT_BLOCKS * 4) {
            float v = x[(size_t)row * 64 + c];
            s += v; q += v * v;
        }
        ssum[threadIdx.x] = s; ssq[threadIdx.x] = q;
        __syncthreads();
        if (threadIdx.x < 64) {
            float S = ssum[threadIdx.x] + ssum[threadIdx.x + 64] + ssum[threadIdx.x + 128] + ssum[threadIdx.x + 192];
            float Q = ssq [threadIdx.x] + ssq [threadIdx.x + 64] + ssq [threadIdx.x + 128] + ssq [threadIdx.x + 192];
            atomicAdd(&g_colsum[threadIdx.x], S);
            atomicAdd(&g_colsumsq[threadIdx.x], Q);
        }
    }
}

// ---------------- scan (exclusive) over counts ----------------
__global__ void scan1_kernel() {
    __shared__ int tmp[1024];
    int gid = blockIdx.x * 1024 + threadIdx.x;
    int v = g_counts[gid];
    tmp[threadIdx.x] = v;
    __syncthreads();
    int val = v;
    for (int off = 1; off < 1024; off <<= 1) {
        int add = (threadIdx.x >= off) ? tmp[threadIdx.x - off] : 0;
        __syncthreads();
        val += add;
        tmp[threadIdx.x] = val;
        __syncthreads();
    }
    g_rowptr[gid] = val - v;           // exclusive, local to block
    if (threadIdx.x == 1023) g_bsums[blockIdx.x] = val;
}

// ---------------- merged: stats finalize (t<64, independent) + block-sum scan ----------------
__global__ void fin_scan2_kernel() {
    __shared__ int tmp[128];
    int t = threadIdx.x;
    if (t < 64) {
        float n = (float)NTOT;
        float mean = g_colsum[t] / n;
        float var  = (g_colsumsq[t] - n * mean * mean) / (n - 1.0f);
        g_mean[t] = mean;
        g_rstd[t] = rsqrtf(var);
    }
    int v = (t < NTOT / 1024) ? g_bsums[t] : 0;
    tmp[t] = v;
    __syncthreads();
    int val = v;
    for (int off = 1; off < 128; off <<= 1) {
        int add = (t >= off) ? tmp[t - off] : 0;
        __syncthreads();
        val += add;
        tmp[t] = val;
        __syncthreads();
    }
    if (t < NTOT / 1024) g_bsums[t] = val - v;   // exclusive
}

__global__ void scan3_kernel() {
    int gid = blockIdx.x * blockDim.x + threadIdx.x;
    if (gid >= NTOT) return;
    int rp = g_rowptr[gid] + g_bsums[gid >> 10];
    g_rowptr[gid] = rp;
    g_cursor[gid] = rp;
    g_dis[gid] = rsqrtf(g_deg[gid]);   // deg >= 1 always (self loop weight 1)
    if (gid == 0) g_rowptr[NTOT] = ETOT;
}

// ---------------- edge pass 2: scatter into CSR (packed int2, w pre-scaled by dis[src]) ----------------
__global__ void edge_scatter_kernel(const int* __restrict__ ei, const float* __restrict__ ea) {
    int e = blockIdx.x * blockDim.x + threadIdx.x;
    if (e >= ETOT) return;
    int dst = ei[ETOT + e];
    int src = ei[e];
    float w = fabsf(((const float2*)ea)[e].x) * g_dis[src];
    int pos = atomicAdd(&g_cursor[dst], 1);
    g_csr[pos] = make_int2(src, __float_as_int(w));
}

// ---------------- panel-resident SGEMM with packed f32x2 FMA ----------------
// GATE_ILV: output column nc corresponds to B row (nc&3)*64 + (nc>>2)   (gate-interleave
// permutation for the LSTM input projection; bias indexed with the same map).
template<int K, int BN, int NTILES, bool TRANSB, bool RELU, bool GATE_ILV>
__global__ void gemmP_kernel(const float* __restrict__ A, const float* __restrict__ Bm,
                             const float* __restrict__ bias, const float* __restrict__ bias2,
                             float* __restrict__ C) {
    constexpr int Nout = BN * NTILES;
    constexpr int TX = BN / 4;
    constexpr int THREADS = TX * 16;
    constexpr int SA = 132;            // float4-aligned rows
    constexpr int SB = BN + 4;
    extern __shared__ float smem[];
    float* sA = smem;                  // [K][SA]  (k-major)
    float* sB = smem + K * SA;         // [K][SB]

    int tid = threadIdx.x;
    int m0 = blockIdx.x * 128;
    int tx = tid % TX;
    int ty = tid / TX;

    constexpr int NF4 = K / 4;
    for (int idx = tid; idx < 128 * NF4; idx += THREADS) {
        int r = idx / NF4, c4 = (idx % NF4) * 4;
        float4 a = *(const float4*)(A + (size_t)(m0 + r) * K + c4);
        sA[(c4    ) * SA + r] = a.x;
        sA[(c4 + 1) * SA + r] = a.y;
        sA[(c4 + 2) * SA + r] = a.z;
        sA[(c4 + 3) * SA + r] = a.w;
    }

    for (int nt = 0; nt < NTILES; nt++) {
        int n0 = nt * BN;
        __syncthreads();
        if (!TRANSB) {
            constexpr int BF4 = BN / 4;
            for (int idx = tid; idx < K * BF4; idx += THREADS) {
                int r = idx / BF4, c = (idx % BF4) * 4;
                float4 b = *(const float4*)(Bm + (size_t)r * Nout + n0 + c);
                *(float4*)&sB[r * SB + c] = b;
            }
        } else {
            constexpr int KF4 = K / 4;
            for (int idx = tid; idx < BN * KF4; idx += THREADS) {
                int n = idx / KF4, k4 = (idx % KF4) * 4;
                int nc = n0 + n;
                int brow = GATE_ILV ? ((nc & 3) * 64 + (nc >> 2)) : nc;
                float4 b = *(const float4*)(Bm + (size_t)brow * K + k4);
                sB[(k4    ) * SB + n] = b.x;
                sB[(k4 + 1) * SB + n] = b.y;
                sB[(k4 + 2) * SB + n] = b.z;
                sB[(k4 + 3) * SB + n] = b.w;
            }
        }
        __syncthreads();

        u64 acc2[4][4];
        #pragma unroll
        for (int i = 0; i < 4; i++)
            #pragma unroll
            for (int j = 0; j < 4; j++) acc2[i][j] = 0ull;

        #pragma unroll 8
        for (int kk = 0; kk < K; kk++) {
            ulonglong2 aa0 = *(const ulonglong2*)&sA[kk * SA + ty * 8];
            ulonglong2 aa1 = *(const ulonglong2*)&sA[kk * SA + ty * 8 + 4];
            float4 b = *(const float4*)&sB[kk * SB + tx * 4];
            u64 b0 = dup2(b.x), b1 = dup2(b.y), b2 = dup2(b.z), b3 = dup2(b.w);
            fma2(acc2[0][0], aa0.x, b0); fma2(acc2[0][1], aa0.x, b1);
            fma2(acc2[0][2], aa0.x, b2); fma2(acc2[0][3], aa0.x, b3);
            fma2(acc2[1][0], aa0.y, b0); fma2(acc2[1][1], aa0.y, b1);
            fma2(acc2[1][2], aa0.y, b2); fma2(acc2[1][3], aa0.y, b3);
            fma2(acc2[2][0], aa1.x, b0); fma2(acc2[2][1], aa1.x, b1);
            fma2(acc2[2][2], aa1.x, b2); fma2(acc2[2][3], aa1.x, b3);
            fma2(acc2[3][0], aa1.y, b0); fma2(acc2[3][1], aa1.y, b1);
            fma2(acc2[3][2], aa1.y, b2); fma2(acc2[3][3], aa1.y, b3);
        }

        int n = n0 + tx * 4;
        float bx = 0.f, by = 0.f, bz = 0.f, bw = 0.f;
        if (GATE_ILV) {
            int jj = n >> 2;
            if (bias)  { bx += bias[jj];  by += bias[64 + jj];  bz += bias[128 + jj];  bw += bias[192 + jj]; }
            if (bias2) { bx += bias2[jj]; by += bias2[64 + jj]; bz += bias2[128 + jj]; bw += bias2[192 + jj]; }
        } else {
            if (bias)  { bx += bias[n];  by += bias[n + 1];  bz += bias[n + 2];  bw += bias[n + 3]; }
            if (bias2) { bx += bias2[n]; by += bias2[n + 1]; bz += bias2[n + 2]; bw += bias2[n + 3]; }
        }
        #pragma unroll
        for (int i2 = 0; i2 < 4; i2++) {
            float c0x, c1x, c0y, c1y, c0z, c1z, c0w, c1w;
            up2(acc2[i2][0], c0x, c1x);
            up2(acc2[i2][1], c0y, c1y);
            up2(acc2[i2][2], c0z, c1z);
            up2(acc2[i2][3], c0w, c1w);
            int m = m0 + ty * 8 + i2 * 2;
            float4 v0 = make_float4(c0x + bx, c0y + by, c0z + bz, c0w + bw);
            float4 v1 = make_float4(c1x + bx, c1y + by, c1z + bz, c1w + bw);
            if (RELU) {
                v0.x = fmaxf(v0.x, 0.f); v0.y = fmaxf(v0.y, 0.f); v0.z = fmaxf(v0.z, 0.f); v0.w = fmaxf(v0.w, 0.f);
                v1.x = fmaxf(v1.x, 0.f); v1.y = fmaxf(v1.y, 0.f); v1.z = fmaxf(v1.z, 0.f); v1.w = fmaxf(v1.w, 0.f);
            }
            *(float4*)(C + (size_t)m * Nout + n)       = v0;
            *(float4*)(C + (size_t)(m + 1) * Nout + n) = v1;
        }
    }
}

// ---------------- conv1 aggregation (float2 lanes), normalization folded into epilogue ----------------
__global__ void agg_x_kernel(const float* __restrict__ x, float* __restrict__ out) {
    int warpId = (blockIdx.x * blockDim.x + threadIdx.x) >> 5;
    int lane = threadIdx.x & 31;
    if (warpId >= NTOT) return;
    int i = warpId;
    int beg = g_rowptr[i], end = g_rowptr[i + 1];
    float di = g_dis[i];
    float accx = 0.f, accy = 0.f, wsum = 0.f;

    for (int e0 = beg; e0 < end; e0 += 32) {
        int cnt = min(32, end - e0);
        int s_l = i; float w_l = 0.f;
        if (lane < cnt) {
            int2 v = g_csr[e0 + lane];
            s_l = v.x;
            w_l = __int_as_float(v.y);
        }
        for (int j = 0; j < cnt; j += 4) {
            int   s0 = __shfl_sync(0xffffffffu, s_l, j);
            int   s1 = __shfl_sync(0xffffffffu, s_l, j + 1);
            int   s2 = __shfl_sync(0xffffffffu, s_l, j + 2);
            int   s3 = __shfl_sync(0xffffffffu, s_l, j + 3);
            float w0 = __shfl_sync(0xffffffffu, w_l, j);
            float w1 = __shfl_sync(0xffffffffu, w_l, j + 1);
            float w2 = __shfl_sync(0xffffffffu, w_l, j + 2);
            float w3 = __shfl_sync(0xffffffffu, w_l, j + 3);
            float2 a0 = ((const float2*)(x + (size_t)s0 * 64))[lane];
            float2 a1 = ((const float2*)(x + (size_t)s1 * 64))[lane];
            float2 a2 = ((const float2*)(x + (size_t)s2 * 64))[lane];
            float2 a3 = ((const float2*)(x + (size_t)s3 * 64))[lane];
            accx += a0.x * w0 + a1.x * w1 + a2.x * w2 + a3.x * w3;
            accy += a0.y * w0 + a1.y * w1 + a2.y * w2 + a3.y * w3;
            wsum += w0 + w1 + w2 + w3;
        }
    }
    float di2 = di * di;
    float coef = di * wsum + di2;
    float2 m  = ((const float2*)g_mean)[lane];
    float2 r  = ((const float2*)g_rstd)[lane];
    float2 xi = ((const float2*)(x + (size_t)i * 64))[lane];
    float2 o;
    o.x = r.x * (di * accx + di2 * xi.x - coef * m.x);
    o.y = r.y * (di * accy + di2 * xi.y - coef * m.y);
    ((float2*)(out + (size_t)i * 64))[lane] = o;
}

// ---------------- conv2 aggregation (float2 lanes): bias+relu epilogue ----------------
__global__ void agg_h_kernel(const float* __restrict__ hpre, const float* __restrict__ bias,
                             float* __restrict__ out) {
    int warpId = (blockIdx.x * blockDim.x + threadIdx.x) >> 5;
    int lane = threadIdx.x & 31;
    if (warpId >= NTOT) return;
    int i = warpId;
    int beg = g_rowptr[i], end = g_rowptr[i + 1];
    float di = g_dis[i];
    float accx = 0.f, accy = 0.f;

    for (int e0 = beg; e0 < end; e0 += 32) {
        int cnt = min(32, end - e0);
        int s_l = i; float w_l = 0.f;
        if (lane < cnt) {
            int2 v = g_csr[e0 + lane];
            s_l = v.x;
            w_l = __int_as_float(v.y);
        }
        for (int j = 0; j < cnt; j += 4) {
            int   s0 = __shfl_sync(0xffffffffu, s_l, j);
            int   s1 = __shfl_sync(0xffffffffu, s_l, j + 1);
            int   s2 = __shfl_sync(0xffffffffu, s_l, j + 2);
            int   s3 = __shfl_sync(0xffffffffu, s_l, j + 3);
            float w0 = __shfl_sync(0xffffffffu, w_l, j);
            float w1 = __shfl_sync(0xffffffffu, w_l, j + 1);
            float w2 = __shfl_sync(0xffffffffu, w_l, j + 2);
            float w3 = __shfl_sync(0xffffffffu, w_l, j + 3);
            float2 a0 = ((const float2*)(hpre + (size_t)s0 * 64))[lane];
            float2 a1 = ((const float2*)(hpre + (size_t)s1 * 64))[lane];
            float2 a2 = ((const float2*)(hpre + (size_t)s2 * 64))[lane];
            float2 a3 = ((const float2*)(hpre + (size_t)s3 * 64))[lane];
            accx += a0.x * w0 + a1.x * w1 + a2.x * w2 + a3.x * w3;
            accy += a0.y * w0 + a1.y * w1 + a2.y * w2 + a3.y * w3;
        }
    }
    float di2 = di * di;
    float2 self = ((const float2*)(hpre + (size_t)i * 64))[lane];
    float2 b    = ((const float2*)bias)[lane];
    float2 o;
    o.x = fmaxf(accx * di + self.x * di2 + b.x, 0.f);
    o.y = fmaxf(accy * di + self.y * di2 + b.y, 0.f);
    ((float2*)(out + (size_t)i * 64))[lane] = o;
}

// ---------------- LSTM: 4 seqs/block, packed f32x2 weights, full-block reduce ----------------
__device__ __forceinline__ float sigm(float x) { return 1.0f / (1.0f + expf(-x)); }

__global__ __launch_bounds__(256) void lstm_kernel(const float* __restrict__ xg,
                                                   const float* __restrict__ w_hh,
                                                   float* __restrict__ hfinal) {
    __shared__ float  h_sm[4][64];
    __shared__ __align__(16) float4 p_sm[4][4][64];   // [seq][kc][j]
    int t = threadIdx.x;
    int j = t & 63, kc = t >> 6;
    int k0 = kc * 16;

    u64 wIF[16], wGO[16];
    #pragma unroll
    for (int kk = 0; kk < 16; kk++) {
        float wi = w_hh[(size_t)(      j) * 64 + k0 + kk];
        float wf = w_hh[(size_t)( 64 + j) * 64 + k0 + kk];
        float wg = w_hh[(size_t)(128 + j) * 64 + k0 + kk];
        float wo = w_hh[(size_t)(192 + j) * 64 + k0 + kk];
        wIF[kk] = pk2(wi, wf);
        wGO[kk] = pk2(wg, wo);
    }
    int seq0 = blockIdx.x * 4;
    int myseq = seq0 + kc;
    int bb = myseq / NODES, nn = myseq % NODES;

    float c_state = 0.f;
    h_sm[kc][j] = 0.f;
    size_t row0 = ((size_t)(bb * TSTEPS) * NODES + nn) * GATES;
    float4 xv = *(const float4*)(xg + row0 + j * 4);
    __syncthreads();

    for (int step = 0; step < TSTEPS; step++) {
        u64 aIF[4], aGO[4];
        #pragma unroll
        for (int s = 0; s < 4; s++) { aIF[s] = 0ull; aGO[s] = 0ull; }
        #pragma unroll
        for (int kk = 0; kk < 16; kk++) {
            #pragma unroll
            for (int s = 0; s < 4; s++) {
                u64 hd = dup2(h_sm[s][k0 + kk]);
                fma2(aIF[s], hd, wIF[kk]);
                fma2(aGO[s], hd, wGO[kk]);
            }
        }
        #pragma unroll
        for (int s = 0; s < 4; s++) {
            float pi, pf, pg, po;
            up2(aIF[s], pi, pf);
            up2(aGO[s], pg, po);
            p_sm[s][kc][j] = make_float4(pi, pf, pg, po);
        }
        __syncthreads();
        {
            float4 nv = make_float4(0.f, 0.f, 0.f, 0.f);
            if (step + 1 < TSTEPS) {
                size_t rown = ((size_t)(bb * TSTEPS + step + 1) * NODES + nn) * GATES;
                nv = *(const float4*)(xg + rown + j * 4);
            }
            float4 p = p_sm[kc][0][j];
            float4 q = p_sm[kc][1][j];
            float4 r = p_sm[kc][2][j];
            float4 w = p_sm[kc][3][j];
            float gi = p.x + q.x + r.x + w.x + xv.x;
            float gf = p.y + q.y + r.y + w.y + xv.y;
            float gg = p.z + q.z + r.z + w.z + xv.z;
            float go = p.w + q.w + r.w + w.w + xv.w;
            c_state = sigm(gf) * c_state + sigm(gi) * tanhf(gg);
            h_sm[kc][j] = sigm(go) * tanhf(c_state);
            xv = nv;
        }
        __syncthreads();
    }
    hfinal[(size_t)myseq * 64 + j] = h_sm[kc][j];
}

// ---------------- head: fc1 + relu + fc2 + softmax ----------------
__global__ void head_kernel(const float* __restrict__ hfinal,
                            const float* __restrict__ fc1_w, const float* __restrict__ fc1_b,
                            const float* __restrict__ fc2_w, const float* __restrict__ fc2_b,
                            float* __restrict__ out) {
    __shared__ float h[64];
    __shared__ float f1[128];
    __shared__ float logits[3];
    int s = blockIdx.x, tid = threadIdx.x;
    if (tid < 64) h[tid] = hfinal[(size_t)s * 64 + tid];
    __syncthreads();
    float acc = fc1_b[tid];
    #pragma unroll 8
    for (int k = 0; k < 64; k++) acc += h[k] * fc1_w[(size_t)tid * 64 + k];
    f1[tid] = fmaxf(acc, 0.f);
    __syncthreads();
    if (tid < 3) {
        float l = fc2_b[tid];
        #pragma unroll 8
        for (int k = 0; k < 128; k++) l += f1[k] * fc2_w[(size_t)tid * 128 + k];
        logits[tid] = l;
    }
    __syncthreads();
    if (tid == 0) {
        float m = fmaxf(logits[0], fmaxf(logits[1], logits[2]));
        float e0 = expf(logits[0] - m), e1 = expf(logits[1] - m), e2 = expf(logits[2] - m);
        float inv = 1.0f / (e0 + e1 + e2);
        out[(size_t)s * 3 + 0] = e0 * inv;
        out[(size_t)s * 3 + 1] = e1 * inv;
        out[(size_t)s * 3 + 2] = e2 * inv;
    }
}

// ---------------- host launcher ----------------
static void* sym_addr(const void* sym) {
    void* p = nullptr;
    cudaGetSymbolAddress(&p, sym);
    return p;
}

extern "C" void kernel_launch(void* const* d_in, const int* in_sizes, int n_in,
                              void* d_out, int out_size) {
    const float* x        = (const float*)d_in[0];
    const float* ea       = (const float*)d_in[1];
    const float* conv1_w  = (const float*)d_in[2];
    const float* conv1_b  = (const float*)d_in[3];
    const float* conv2_w  = (const float*)d_in[4];
    const float* conv2_b  = (const float*)d_in[5];
    const float* w_ih     = (const float*)d_in[6];
    const float* w_hh     = (const float*)d_in[7];
    const float* b_ih     = (const float*)d_in[8];
    const float* b_hh     = (const float*)d_in[9];
    const float* fc1_w    = (const float*)d_in[10];
    const float* fc1_b    = (const float*)d_in[11];
    const float* fc2_w    = (const float*)d_in[12];
    const float* fc2_b    = (const float*)d_in[13];
    const int*   ei       = (const int*)d_in[14];
    float* out = (float*)d_out;

    float* aggx  = (float*)sym_addr(g_aggx);
    float* h1    = (float*)sym_addr(g_h1);
    float* h2pre = (float*)sym_addr(g_h2pre);
    float* h2    = (float*)sym_addr(g_h2);
    float* xg    = (float*)sym_addr(g_xg);
    float* hfin  = (float*)sym_addr(g_hfin);

    // GEMM instantiations + smem sizes
    auto g1 = gemmP_kernel<64, 96, 1, false, true,  false>;   // aggx@W1 (+b1, relu) -> h1
    auto g2 = gemmP_kernel<96, 64, 1, false, false, false>;   // h1@W2            -> h2pre
    auto g3 = gemmP_kernel<64, 64, 4, true,  false, true >;   // h2@w_ih^T (+b)   -> xg (gate-ilv)
    size_t s1 = (size_t)(64 * 132 + 64 * 100) * 4;
    size_t s2 = (size_t)(96 * 132 + 96 * 68 ) * 4;
    size_t s3 = (size_t)(64 * 132 + 64 * 68 ) * 4;
    cudaFuncSetAttribute(g1, cudaFuncAttributeMaxDynamicSharedMemorySize, (int)s1);
    cudaFuncSetAttribute(g2, cudaFuncAttributeMaxDynamicSharedMemorySize, (int)s2);
    cudaFuncSetAttribute(g3, cudaFuncAttributeMaxDynamicSharedMemorySize, (int)s3);

    // preprocessing: init -> fused(edge hist + col stats) -> scan chain -> scatter
    init_kernel<<<(NTOT + 255) / 256, 256>>>();
    stats_edge_kernel<<<EDGE_BLOCKS + STAT_BLOCKS, 256>>>(x, ei, ea);
    scan1_kernel<<<NTOT / 1024, 1024>>>();
    fin_scan2_kernel<<<1, 128>>>();
    scan3_kernel<<<(NTOT + 255) / 256, 256>>>();
    edge_scatter_kernel<<<ETOT / 256, 256>>>(ei, ea);

    // conv1 (reordered): aggx = agg(norm(x));  h1 = relu(aggx @ W1 + b1)
    agg_x_kernel<<<NTOT / 8, 256>>>(x, aggx);
    g1<<<NTOT / 128, 384, s1>>>(aggx, conv1_w, conv1_b, nullptr, h1);

    // conv2: h2 = relu(agg(h1 @ W2) + b2)
    g2<<<NTOT / 128, 256, s2>>>(h1, conv2_w, nullptr, nullptr, h2pre);
    agg_h_kernel<<<NTOT / 8, 256>>>(h2pre, conv2_b, h2);

    // LSTM input projection (gate-interleaved output): xg[row][j*4+g]
    g3<<<NTOT / 128, 256, s3>>>(h2, w_ih, b_ih, b_hh, xg);

    // recurrence: 4 seqs/block, full-block reduce
    lstm_kernel<<<NSEQ / 4, 256>>>(xg, w_hh, hfin);

    // head
    head_kernel<<<NSEQ, 128>>>(hfin, fc1_w, fc1_b, fc2_w, fc2_b, out);
}